// round 12
// baseline (speedup 1.0000x reference)
#include <cuda_runtime.h>
#include <cuda_bf16.h>
#include <cstddef>

// Problem constants
#define Vv   50000
#define Ee   128
#define Cc   128
#define Hh   4
#define Ll   4
#define HSs  32
#define FFf  512
#define Bb   32
#define Rr   (Bb * Cc)        // 4096 rows
#define SCALE 0.08838834764831845f   // 1/sqrt(128) (reference scales by ctx_length**0.5)

// ---------------- scratch (static device globals; no allocation) ----------------
__device__ float g_x[Rr * Ee];     // residual stream
__device__ float g_h[Rr * Ee];     // LN output
__device__ float g_k[Rr * Ee];     // (B,H,C,HS)
__device__ float g_v[Rr * Ee];     // (B,H,C,HS)
__device__ float g_att[Rr * Ee];   // attention out in (B,C,E)
__device__ float g_u[Rr * FFf];    // FFN intermediate (post-relu)

// ---------------- embedding gather ----------------
__global__ void embed_kernel(const int* __restrict__ idx,
                             const float* __restrict__ te,
                             const float* __restrict__ pe) {
    int r = blockIdx.x;
    int t = threadIdx.x;
    int tok = idx[r];
    size_t off = (size_t)tok * Ee + t;
    g_x[r * Ee + t] = te[off] + pe[off];
}

// ---------------- LayerNorm (x -> h). unbiased: ddof=1 ----------------
__global__ void ln_kernel(const float* __restrict__ g,
                          const float* __restrict__ b,
                          int unbiased) {
    int r = blockIdx.x;
    int t = threadIdx.x;
    float v = g_x[r * Ee + t];

    __shared__ float red[4];
    float s = v;
#pragma unroll
    for (int o = 16; o; o >>= 1) s += __shfl_down_sync(0xffffffffu, s, o);
    if ((t & 31) == 0) red[t >> 5] = s;
    __syncthreads();
    float mean = (red[0] + red[1] + red[2] + red[3]) * (1.0f / Ee);
    float d = v - mean;
    float q = d * d;
#pragma unroll
    for (int o = 16; o; o >>= 1) q += __shfl_down_sync(0xffffffffu, q, o);
    __syncthreads();
    if ((t & 31) == 0) red[t >> 5] = q;
    __syncthreads();
    float inv_n = unbiased ? (1.0f / (Ee - 1)) : (1.0f / Ee);
    float var = (red[0] + red[1] + red[2] + red[3]) * inv_n;
    g_h[r * Ee + t] = d * rsqrtf(var + 1e-5f) * g[t] + b[t];
}

// ---------------- K/V projection: k[b,h,c,f] = h_row . Wk[h,:,f] + bk ----------------
#define KV_RPB 8
__global__ void kv_kernel(const float* __restrict__ Wk, const float* __restrict__ bk,
                          const float* __restrict__ Wv, const float* __restrict__ bv) {
    __shared__ float sh[KV_RPB * Ee];
    int r0 = blockIdx.x * KV_RPB;
    int t = threadIdx.x;   // 128
#pragma unroll
    for (int i = 0; i < KV_RPB; ++i) sh[i * Ee + t] = g_h[(r0 + i) * Ee + t];
    __syncthreads();

    int hd = t >> 5, f = t & 31;
    float ak[KV_RPB], av[KV_RPB];
#pragma unroll
    for (int i = 0; i < KV_RPB; ++i) { ak[i] = 0.f; av[i] = 0.f; }

    const float* wkp = Wk + (size_t)hd * Ee * HSs + f;
    const float* wvp = Wv + (size_t)hd * Ee * HSs + f;
#pragma unroll 4
    for (int e = 0; e < Ee; ++e) {
        float wk = wkp[e * HSs];
        float wv = wvp[e * HSs];
#pragma unroll
        for (int i = 0; i < KV_RPB; ++i) {
            float hv = sh[i * Ee + e];
            ak[i] += hv * wk;
            av[i] += hv * wv;
        }
    }
    float bkv = bk[hd * HSs + f];
    float bvv = bv[hd * HSs + f];
#pragma unroll
    for (int i = 0; i < KV_RPB; ++i) {
        int r = r0 + i;
        int bb = r >> 7, cc = r & 127;
        size_t o = (((size_t)bb * Hh + hd) * Cc + cc) * HSs + f;
        g_k[o] = ak[i] + bkv;
        g_v[o] = av[i] + bvv;
    }
}

// ---------------- attention: scores = k@k^T * scale (bug preserved), causal softmax, @v ----------------
__global__ void attn_kernel() {
    int bh = blockIdx.x;            // b*H + h
    int b = bh >> 2, h = bh & 3;
    int c = threadIdx.x;            // 0..127

    __shared__ float ks[Cc][HSs + 1];
    __shared__ float vs[Cc][HSs + 1];
    const float* kbase = g_k + (size_t)bh * Cc * HSs;
    const float* vbase = g_v + (size_t)bh * Cc * HSs;
#pragma unroll
    for (int i = 0; i < 32; ++i) {
        int id = c + i * 128;
        int row = id >> 5, f = id & 31;
        ks[row][f] = kbase[id];
        vs[row][f] = vbase[id];
    }
    __syncthreads();

    float kr[HSs];
#pragma unroll
    for (int f = 0; f < HSs; ++f) kr[f] = ks[c][f];

    float o[HSs];
#pragma unroll
    for (int f = 0; f < HSs; ++f) o[f] = 0.f;
    float m = -1e30f, Z = 0.f;

    for (int c2 = 0; c2 <= c; ++c2) {
        // split dot accumulation to break dependency chain
        float s0 = 0.f, s1 = 0.f, s2 = 0.f, s3 = 0.f;
#pragma unroll
        for (int f = 0; f < HSs; f += 4) {
            s0 += kr[f + 0] * ks[c2][f + 0];
            s1 += kr[f + 1] * ks[c2][f + 1];
            s2 += kr[f + 2] * ks[c2][f + 2];
            s3 += kr[f + 3] * ks[c2][f + 3];
        }
        float s = ((s0 + s1) + (s2 + s3)) * SCALE;
        float nm = fmaxf(m, s);
        float alpha = __expf(m - nm);
        float w = __expf(s - nm);
        Z = Z * alpha + w;
#pragma unroll
        for (int f = 0; f < HSs; ++f) o[f] = o[f] * alpha + w * vs[c2][f];
        m = nm;
    }
    float inv = 1.0f / Z;
    float* orow = g_att + ((size_t)(b * Cc + c)) * Ee + h * HSs;
#pragma unroll
    for (int f = 0; f < HSs; ++f) orow[f] = o[f] * inv;
}

// ---------------- output projection + residual: x += att @ Wo + bo ----------------
__global__ void proj_kernel(const float* __restrict__ Wo, const float* __restrict__ bo) {
    __shared__ float sa[8 * Ee];
    int r0 = blockIdx.x * 8;
    int t = threadIdx.x;  // 128
#pragma unroll
    for (int i = 0; i < 8; ++i) sa[i * Ee + t] = g_att[(r0 + i) * Ee + t];
    __syncthreads();
    float acc[8];
#pragma unroll
    for (int i = 0; i < 8; ++i) acc[i] = 0.f;
#pragma unroll 4
    for (int e = 0; e < Ee; ++e) {
        float w = Wo[e * Ee + t];
#pragma unroll
        for (int i = 0; i < 8; ++i) acc[i] += sa[i * Ee + e] * w;
    }
    float bb = bo[t];
#pragma unroll
    for (int i = 0; i < 8; ++i) g_x[(r0 + i) * Ee + t] += acc[i] + bb;
}

// ---------------- FFN1: u = relu(h @ W1 + b1) ----------------
__global__ void ffn1_kernel(const float* __restrict__ W1, const float* __restrict__ b1) {
    __shared__ float sh[8 * Ee];
    int r0 = blockIdx.x * 8;
    int t = threadIdx.x;  // 256
    for (int i = t; i < 8 * Ee; i += 256) sh[i] = g_h[r0 * Ee + i];
    __syncthreads();
    float acc0[8], acc1[8];
#pragma unroll
    for (int i = 0; i < 8; ++i) { acc0[i] = 0.f; acc1[i] = 0.f; }
#pragma unroll 4
    for (int e = 0; e < Ee; ++e) {
        float w0 = W1[e * FFf + t];
        float w1 = W1[e * FFf + t + 256];
#pragma unroll
        for (int i = 0; i < 8; ++i) {
            float hv = sh[i * Ee + e];
            acc0[i] += hv * w0;
            acc1[i] += hv * w1;
        }
    }
    float bb0 = b1[t], bb1 = b1[t + 256];
#pragma unroll
    for (int i = 0; i < 8; ++i) {
        g_u[(r0 + i) * FFf + t]       = fmaxf(acc0[i] + bb0, 0.f);
        g_u[(r0 + i) * FFf + t + 256] = fmaxf(acc1[i] + bb1, 0.f);
    }
}

// ---------------- FFN2 + residual: x += u @ W2 + b2 ----------------
__global__ void ffn2_kernel(const float* __restrict__ W2, const float* __restrict__ b2) {
    __shared__ float su[8 * FFf];   // 16 KB
    int r0 = blockIdx.x * 8;
    int t = threadIdx.x;  // 128
    for (int i = t; i < 8 * FFf; i += 128) su[i] = g_u[r0 * FFf + i];
    __syncthreads();
    float acc[8];
#pragma unroll
    for (int i = 0; i < 8; ++i) acc[i] = 0.f;
#pragma unroll 4
    for (int jf = 0; jf < FFf; ++jf) {
        float w = W2[jf * Ee + t];
#pragma unroll
        for (int i = 0; i < 8; ++i) acc[i] += su[i * FFf + jf] * w;
    }
    float bb = b2[t];
#pragma unroll
    for (int i = 0; i < 8; ++i) g_x[(r0 + i) * Ee + t] += acc[i] + bb;
}

// ---------------- final LM head GEMM: out = h @ Wf + bf ----------------
// BM=32 rows, BN=128 cols, BK=16, 256 threads, 4x4 microtile per thread
__global__ void lmhead_kernel(const float* __restrict__ Wf,
                              const float* __restrict__ bf,
                              float* __restrict__ out) {
    __shared__ float As[32][Ee];    // 16 KB
    __shared__ float Bs[16][128];   //  8 KB
    int tid  = threadIdx.x;
    int row0 = blockIdx.y * 32;
    int col0 = blockIdx.x * 128;

    // load A tile (32x128) with float4
#pragma unroll
    for (int i = 0; i < 4; ++i) {
        int id4 = tid + i * 256;        // 0..1023
        int m   = id4 >> 5;             // 0..31
        int e4  = (id4 & 31) << 2;      // 0..124
        float4 a = *(const float4*)(&g_h[(row0 + m) * Ee + e4]);
        *(float4*)&As[m][e4] = a;
    }

    float acc[4][4];
#pragma unroll
    for (int i = 0; i < 4; ++i)
#pragma unroll
        for (int j = 0; j < 4; ++j) acc[i][j] = 0.f;

    int tn4 = (tid & 31) << 2;   // 0..124
    int tm4 = (tid >> 5) << 2;   // 0..28

    for (int k0 = 0; k0 < Ee; k0 += 16) {
        __syncthreads();
        // stage B chunk (16x128)
#pragma unroll
        for (int i = 0; i < 2; ++i) {
            int id4 = tid + i * 256;     // 0..511
            int kk  = id4 >> 5;          // 0..15
            int c4  = (id4 & 31) << 2;   // 0..124
            int col = col0 + c4;
            float4 bv;
            if (col < Vv) bv = *(const float4*)(Wf + (size_t)(k0 + kk) * Vv + col);
            else          bv = make_float4(0.f, 0.f, 0.f, 0.f);
            *(float4*)&Bs[kk][c4] = bv;
        }
        __syncthreads();
#pragma unroll
        for (int kk = 0; kk < 16; ++kk) {
            float4 bv = *(const float4*)&Bs[kk][tn4];
            float a0 = As[tm4 + 0][k0 + kk];
            float a1 = As[tm4 + 1][k0 + kk];
            float a2 = As[tm4 + 2][k0 + kk];
            float a3 = As[tm4 + 3][k0 + kk];
            acc[0][0] += a0 * bv.x; acc[0][1] += a0 * bv.y; acc[0][2] += a0 * bv.z; acc[0][3] += a0 * bv.w;
            acc[1][0] += a1 * bv.x; acc[1][1] += a1 * bv.y; acc[1][2] += a1 * bv.z; acc[1][3] += a1 * bv.w;
            acc[2][0] += a2 * bv.x; acc[2][1] += a2 * bv.y; acc[2][2] += a2 * bv.z; acc[2][3] += a2 * bv.w;
            acc[3][0] += a3 * bv.x; acc[3][1] += a3 * bv.y; acc[3][2] += a3 * bv.z; acc[3][3] += a3 * bv.w;
        }
    }

    int col = col0 + tn4;
    if (col < Vv) {
        float4 b4 = *(const float4*)(bf + col);
#pragma unroll
        for (int i = 0; i < 4; ++i) {
            float4 r;
            r.x = acc[i][0] + b4.x;
            r.y = acc[i][1] + b4.y;
            r.z = acc[i][2] + b4.z;
            r.w = acc[i][3] + b4.w;
            *(float4*)(out + (size_t)(row0 + tm4 + i) * Vv + col) = r;
        }
    }
}

// ---------------- launcher ----------------
extern "C" void kernel_launch(void* const* d_in, const int* in_sizes, int n_in,
                              void* d_out, int out_size) {
    const int*   idx  = (const int*)  d_in[0];
    const float* tok  = (const float*)d_in[1];
    const float* pos  = (const float*)d_in[2];
    const float* Wk   = (const float*)d_in[3];
    const float* bk   = (const float*)d_in[4];
    const float* Wv   = (const float*)d_in[5];
    const float* bv   = (const float*)d_in[6];
    const float* Wo   = (const float*)d_in[7];
    const float* bo   = (const float*)d_in[8];
    const float* W1   = (const float*)d_in[9];
    const float* b1   = (const float*)d_in[10];
    const float* W2   = (const float*)d_in[11];
    const float* b2   = (const float*)d_in[12];
    const float* ln1g = (const float*)d_in[13];
    const float* ln1b = (const float*)d_in[14];
    const float* ln2g = (const float*)d_in[15];
    const float* ln2b = (const float*)d_in[16];
    const float* lnfg = (const float*)d_in[17];
    const float* lnfb = (const float*)d_in[18];
    const float* Wf   = (const float*)d_in[19];
    const float* bf   = (const float*)d_in[20];
    float* out = (float*)d_out;

    embed_kernel<<<Rr, 128>>>(idx, tok, pos);

    for (int l = 0; l < Ll; ++l) {
        ln_kernel<<<Rr, 128>>>(ln1g + l * Ee, ln1b + l * Ee, 1);
        kv_kernel<<<Rr / KV_RPB, 128>>>(Wk + (size_t)l * Hh * Ee * HSs,
                                        bk + (size_t)l * Hh * HSs,
                                        Wv + (size_t)l * Hh * Ee * HSs,
                                        bv + (size_t)l * Hh * HSs);
        attn_kernel<<<Bb * Hh, 128>>>();
        proj_kernel<<<Rr / 8, 128>>>(Wo + (size_t)l * Ee * Ee, bo + (size_t)l * Ee);
        ln_kernel<<<Rr, 128>>>(ln2g + l * Ee, ln2b + l * Ee, 1);
        ffn1_kernel<<<Rr / 8, 256>>>(W1 + (size_t)l * Ee * FFf, b1 + (size_t)l * FFf);
        ffn2_kernel<<<Rr / 8, 128>>>(W2 + (size_t)l * FFf * Ee, b2 + (size_t)l * Ee);
    }

    ln_kernel<<<Rr, 128>>>(lnfg, lnfb, 0);

    dim3 grid((Vv + 127) / 128, Rr / 32);
    lmhead_kernel<<<grid, 256>>>(Wf, bf, out);
}

// round 13
// speedup vs baseline: 1.6533x; 1.6533x over previous
#include <cuda_runtime.h>
#include <cuda_bf16.h>
#include <cstddef>

// Problem constants
#define Vv   50000
#define Ee   128
#define Cc   128
#define Hh   4
#define Ll   4
#define HSs  32
#define FFf  512
#define Bb   32
#define Rr   (Bb * Cc)        // 4096 rows
#define SCALE 0.08838834764831845f   // 1/sqrt(128)

// ---------------- scratch (static device globals; no allocation) ----------------
__device__ float g_x[Rr * Ee];         // residual stream
__device__ float g_h[Rr * Ee];         // LN output
__device__ float g_k[Rr * Ee];         // (B,H,C,HS)
__device__ float g_v[Rr * Ee];         // (B,H,C,HS)
__device__ float g_att[Rr * Ee];       // attention out in (B,C,E)
__device__ float g_u[Rr * FFf];        // FFN intermediate (post-relu)
__device__ unsigned g_ha[Rr * Ee];     // tf32 final-LN activations
__device__ unsigned g_wft[Ee * Vv];    // tf32 Wf (25.6 MB)

// ---------------- tf32 convert helpers ----------------
__device__ __forceinline__ unsigned f2tf32(float f) {
    unsigned o;
    asm("cvt.rna.tf32.f32 %0, %1;" : "=r"(o) : "f"(f));
    return o;
}

__global__ void cvt_wf_kernel(const float* __restrict__ src) {
    int i = blockIdx.x * blockDim.x + threadIdx.x;   // uint4 index, 1.6M total
    float4 v = ((const float4*)src)[i];
    uint4 o;
    o.x = f2tf32(v.x); o.y = f2tf32(v.y); o.z = f2tf32(v.z); o.w = f2tf32(v.w);
    ((uint4*)g_wft)[i] = o;
}

__global__ void cvt_h_kernel() {
    int i = blockIdx.x * blockDim.x + threadIdx.x;   // 131072 total
    float4 v = ((const float4*)g_h)[i];
    uint4 o;
    o.x = f2tf32(v.x); o.y = f2tf32(v.y); o.z = f2tf32(v.z); o.w = f2tf32(v.w);
    ((uint4*)g_ha)[i] = o;
}

// ---------------- embedding gather ----------------
__global__ void embed_kernel(const int* __restrict__ idx,
                             const float* __restrict__ te,
                             const float* __restrict__ pe) {
    int r = blockIdx.x;
    int t = threadIdx.x;
    int tok = idx[r];
    size_t off = (size_t)tok * Ee + t;
    g_x[r * Ee + t] = te[off] + pe[off];
}

// ---------------- LayerNorm (x -> h) ----------------
__global__ void ln_kernel(const float* __restrict__ g,
                          const float* __restrict__ b,
                          int unbiased) {
    int r = blockIdx.x;
    int t = threadIdx.x;
    float v = g_x[r * Ee + t];

    __shared__ float red[4];
    float s = v;
#pragma unroll
    for (int o = 16; o; o >>= 1) s += __shfl_down_sync(0xffffffffu, s, o);
    if ((t & 31) == 0) red[t >> 5] = s;
    __syncthreads();
    float mean = (red[0] + red[1] + red[2] + red[3]) * (1.0f / Ee);
    float d = v - mean;
    float q = d * d;
#pragma unroll
    for (int o = 16; o; o >>= 1) q += __shfl_down_sync(0xffffffffu, q, o);
    __syncthreads();
    if ((t & 31) == 0) red[t >> 5] = q;
    __syncthreads();
    float inv_n = unbiased ? (1.0f / (Ee - 1)) : (1.0f / Ee);
    float var = (red[0] + red[1] + red[2] + red[3]) * inv_n;
    g_h[r * Ee + t] = d * rsqrtf(var + 1e-5f) * g[t] + b[t];
}

// ---------------- K/V projection ----------------
#define KV_RPB 8
__global__ void kv_kernel(const float* __restrict__ Wk, const float* __restrict__ bk,
                          const float* __restrict__ Wv, const float* __restrict__ bv) {
    __shared__ float sh[KV_RPB * Ee];
    int r0 = blockIdx.x * KV_RPB;
    int t = threadIdx.x;   // 128
#pragma unroll
    for (int i = 0; i < KV_RPB; ++i) sh[i * Ee + t] = g_h[(r0 + i) * Ee + t];
    __syncthreads();

    int hd = t >> 5, f = t & 31;
    float ak[KV_RPB], av[KV_RPB];
#pragma unroll
    for (int i = 0; i < KV_RPB; ++i) { ak[i] = 0.f; av[i] = 0.f; }

    const float* wkp = Wk + (size_t)hd * Ee * HSs + f;
    const float* wvp = Wv + (size_t)hd * Ee * HSs + f;
#pragma unroll 4
    for (int e = 0; e < Ee; ++e) {
        float wk = wkp[e * HSs];
        float wv = wvp[e * HSs];
#pragma unroll
        for (int i = 0; i < KV_RPB; ++i) {
            float hv = sh[i * Ee + e];
            ak[i] += hv * wk;
            av[i] += hv * wv;
        }
    }
    float bkv = bk[hd * HSs + f];
    float bvv = bv[hd * HSs + f];
#pragma unroll
    for (int i = 0; i < KV_RPB; ++i) {
        int r = r0 + i;
        int bb = r >> 7, cc = r & 127;
        size_t o = (((size_t)bb * Hh + hd) * Cc + cc) * HSs + f;
        g_k[o] = ak[i] + bkv;
        g_v[o] = av[i] + bvv;
    }
}

// ---------------- attention (two-pass, smem score tile) ----------------
// grid = 128 (b*H+h), 256 threads. dyn smem: K(16KB) V(16KB) S(128x133 f32)
#define ATT_SSTRIDE 133
#define ATT_SMEM (Cc*HSs*4 + Cc*HSs*4 + Cc*ATT_SSTRIDE*4)
__global__ void attn_kernel() {
    extern __shared__ float dsm[];
    float* Kt = dsm;                         // [128][32]
    float* Vt = dsm + Cc * HSs;              // [128][32]
    float* S  = dsm + 2 * Cc * HSs;          // [128][133]
    __shared__ float Sm[2][Cc];
    __shared__ float Zp[2][Cc];

    int bh = blockIdx.x;
    int b = bh >> 2, h = bh & 3;
    int t = threadIdx.x;          // 0..255
    int c = t & 127;
    int half = t >> 7;            // 0/1

    // load K,V (contiguous per bh)
    const float4* kb = (const float4*)(g_k + (size_t)bh * Cc * HSs);
    const float4* vb = (const float4*)(g_v + (size_t)bh * Cc * HSs);
#pragma unroll
    for (int i = 0; i < 4; ++i) {
        ((float4*)Kt)[t + i * 256] = kb[t + i * 256];
        ((float4*)Vt)[t + i * 256] = vb[t + i * 256];
    }
    __syncthreads();

    // my query row (= key row, bug preserved)
    float4 kr[8];
    const float4* krow = (const float4*)(Kt + c * HSs);
#pragma unroll
    for (int q = 0; q < 8; ++q) kr[q] = krow[q];

    // phase 2: scores for c2 in [half*64, half*64+64)
    int c2base = half * 64;
    float mh = -1e30f;
    const float4* K4 = (const float4*)Kt;
#pragma unroll 4
    for (int j = 0; j < 64; ++j) {
        int c2 = c2base + j;
        float s0 = 0.f, s1 = 0.f, s2 = 0.f, s3 = 0.f;
#pragma unroll
        for (int q = 0; q < 8; q += 2) {
            float4 a = K4[c2 * 8 + q];
            float4 bq = K4[c2 * 8 + q + 1];
            s0 += kr[q].x * a.x;     s1 += kr[q].y * a.y;
            s2 += kr[q].z * a.z;     s3 += kr[q].w * a.w;
            s0 += kr[q + 1].x * bq.x; s1 += kr[q + 1].y * bq.y;
            s2 += kr[q + 1].z * bq.z; s3 += kr[q + 1].w * bq.w;
        }
        float s = ((s0 + s1) + (s2 + s3)) * SCALE;
        float sv = (c2 <= c) ? s : -INFINITY;
        S[c * ATT_SSTRIDE + c2] = sv;
        mh = fmaxf(mh, sv);
    }
    Sm[half][c] = mh;
    __syncthreads();
    float m = fmaxf(Sm[0][c], Sm[1][c]);

    // exp pass (masked entries -> 0)
    float z = 0.f;
#pragma unroll 4
    for (int j = 0; j < 64; ++j) {
        int c2 = c2base + j;
        float e = __expf(S[c * ATT_SSTRIDE + c2] - m);
        S[c * ATT_SSTRIDE + c2] = e;
        z += e;
    }
    Zp[half][c] = z;
    __syncthreads();
    float inv = 1.0f / (Zp[0][c] + Zp[1][c]);

    // phase 3: O = P @ V ; thread covers f in [half*16, half*16+16)
    int fb = half * 16;
    float4 a0 = {0,0,0,0}, a1 = {0,0,0,0}, a2 = {0,0,0,0}, a3 = {0,0,0,0};
    const float4* V4 = (const float4*)Vt;
#pragma unroll 4
    for (int c2 = 0; c2 < Cc; ++c2) {
        float p = S[c * ATT_SSTRIDE + c2];
        const float4* vr = V4 + c2 * 8 + (fb >> 2);
        float4 v0 = vr[0], v1 = vr[1], v2 = vr[2], v3 = vr[3];
        a0.x += p * v0.x; a0.y += p * v0.y; a0.z += p * v0.z; a0.w += p * v0.w;
        a1.x += p * v1.x; a1.y += p * v1.y; a1.z += p * v1.z; a1.w += p * v1.w;
        a2.x += p * v2.x; a2.y += p * v2.y; a2.z += p * v2.z; a2.w += p * v2.w;
        a3.x += p * v3.x; a3.y += p * v3.y; a3.z += p * v3.z; a3.w += p * v3.w;
    }
    float* orow = g_att + ((size_t)(b * Cc + c)) * Ee + h * HSs + fb;
    a0.x *= inv; a0.y *= inv; a0.z *= inv; a0.w *= inv;
    a1.x *= inv; a1.y *= inv; a1.z *= inv; a1.w *= inv;
    a2.x *= inv; a2.y *= inv; a2.z *= inv; a2.w *= inv;
    a3.x *= inv; a3.y *= inv; a3.z *= inv; a3.w *= inv;
    ((float4*)orow)[0] = a0; ((float4*)orow)[1] = a1;
    ((float4*)orow)[2] = a2; ((float4*)orow)[3] = a3;
}

// ---------------- output projection + residual ----------------
__global__ void proj_kernel(const float* __restrict__ Wo, const float* __restrict__ bo) {
    __shared__ float sa[8 * Ee];
    int r0 = blockIdx.x * 8;
    int t = threadIdx.x;  // 128
#pragma unroll
    for (int i = 0; i < 8; ++i) sa[i * Ee + t] = g_att[(r0 + i) * Ee + t];
    __syncthreads();
    float acc[8];
#pragma unroll
    for (int i = 0; i < 8; ++i) acc[i] = 0.f;
#pragma unroll 4
    for (int e = 0; e < Ee; ++e) {
        float w = Wo[e * Ee + t];
#pragma unroll
        for (int i = 0; i < 8; ++i) acc[i] += sa[i * Ee + e] * w;
    }
    float bb = bo[t];
#pragma unroll
    for (int i = 0; i < 8; ++i) g_x[(r0 + i) * Ee + t] += acc[i] + bb;
}

// ---------------- FFN1 ----------------
__global__ void ffn1_kernel(const float* __restrict__ W1, const float* __restrict__ b1) {
    __shared__ float sh[8 * Ee];
    int r0 = blockIdx.x * 8;
    int t = threadIdx.x;  // 256
    for (int i = t; i < 8 * Ee; i += 256) sh[i] = g_h[r0 * Ee + i];
    __syncthreads();
    float acc0[8], acc1[8];
#pragma unroll
    for (int i = 0; i < 8; ++i) { acc0[i] = 0.f; acc1[i] = 0.f; }
#pragma unroll 4
    for (int e = 0; e < Ee; ++e) {
        float w0 = W1[e * FFf + t];
        float w1 = W1[e * FFf + t + 256];
#pragma unroll
        for (int i = 0; i < 8; ++i) {
            float hv = sh[i * Ee + e];
            acc0[i] += hv * w0;
            acc1[i] += hv * w1;
        }
    }
    float bb0 = b1[t], bb1 = b1[t + 256];
#pragma unroll
    for (int i = 0; i < 8; ++i) {
        g_u[(r0 + i) * FFf + t]       = fmaxf(acc0[i] + bb0, 0.f);
        g_u[(r0 + i) * FFf + t + 256] = fmaxf(acc1[i] + bb1, 0.f);
    }
}

// ---------------- FFN2 + residual ----------------
__global__ void ffn2_kernel(const float* __restrict__ W2, const float* __restrict__ b2) {
    __shared__ float su[8 * FFf];
    int r0 = blockIdx.x * 8;
    int t = threadIdx.x;  // 128
    for (int i = t; i < 8 * FFf; i += 128) su[i] = g_u[r0 * FFf + i];
    __syncthreads();
    float acc[8];
#pragma unroll
    for (int i = 0; i < 8; ++i) acc[i] = 0.f;
#pragma unroll 4
    for (int jf = 0; jf < FFf; ++jf) {
        float w = W2[jf * Ee + t];
#pragma unroll
        for (int i = 0; i < 8; ++i) acc[i] += su[i * FFf + jf] * w;
    }
    float bb = b2[t];
#pragma unroll
    for (int i = 0; i < 8; ++i) g_x[(r0 + i) * Ee + t] += acc[i] + bb;
}

// ---------------- LM head: tf32 mma.sync, BM=128 BN=128 K=128 ----------------
// smem: As[128][132] u32 + Bs[128][136] u32 = 137216 bytes
#define LM_ASTRIDE 132
#define LM_BSTRIDE 136
#define LM_SMEM ((128 * LM_ASTRIDE + 128 * LM_BSTRIDE) * 4)

__device__ __forceinline__ void mma_tf32(float c[4],
                                         unsigned a0, unsigned a1, unsigned a2, unsigned a3,
                                         unsigned b0, unsigned b1) {
    asm volatile(
        "mma.sync.aligned.m16n8k8.row.col.f32.tf32.tf32.f32 "
        "{%0,%1,%2,%3}, {%4,%5,%6,%7}, {%8,%9}, {%0,%1,%2,%3};\n"
        : "+f"(c[0]), "+f"(c[1]), "+f"(c[2]), "+f"(c[3])
        : "r"(a0), "r"(a1), "r"(a2), "r"(a3), "r"(b0), "r"(b1));
}

__global__ __launch_bounds__(256, 1)
void lmhead_kernel(const float* __restrict__ bf, float* __restrict__ out) {
    extern __shared__ unsigned usm[];
    unsigned* As = usm;                       // [128][132]
    unsigned* Bs = usm + 128 * LM_ASTRIDE;    // [128][136]

    int tid  = threadIdx.x;
    int row0 = blockIdx.y * 128;
    int col0 = blockIdx.x * 128;

    // load A tile (128x128 tf32)
#pragma unroll
    for (int i = 0; i < 16; ++i) {
        int id4 = tid + i * 256;            // 0..4095
        int m   = id4 >> 5;
        int e4  = (id4 & 31) << 2;
        uint4 a = *(const uint4*)(g_ha + (row0 + m) * Ee + e4);
        *(uint4*)(&As[m * LM_ASTRIDE + e4]) = a;
    }
    // load B tile (128x128 tf32) with tail guard
#pragma unroll
    for (int i = 0; i < 16; ++i) {
        int id4 = tid + i * 256;
        int k   = id4 >> 5;
        int c4  = (id4 & 31) << 2;
        int col = col0 + c4;
        uint4 bv;
        if (col + 3 < Vv) {
            bv = *(const uint4*)(g_wft + (size_t)k * Vv + col);
        } else {
            bv.x = (col     < Vv) ? g_wft[(size_t)k * Vv + col]     : 0u;
            bv.y = (col + 1 < Vv) ? g_wft[(size_t)k * Vv + col + 1] : 0u;
            bv.z = (col + 2 < Vv) ? g_wft[(size_t)k * Vv + col + 2] : 0u;
            bv.w = (col + 3 < Vv) ? g_wft[(size_t)k * Vv + col + 3] : 0u;
        }
        *(uint4*)(&Bs[k * LM_BSTRIDE + c4]) = bv;
    }
    __syncthreads();

    float c[16][4];
#pragma unroll
    for (int fn = 0; fn < 16; ++fn)
#pragma unroll
        for (int j = 0; j < 4; ++j) c[fn][j] = 0.f;

    int lane = tid & 31;
    int grp  = lane >> 2;     // 0..7
    int tig  = lane & 3;      // 0..3
    int wm16 = (tid >> 5) * 16;

#pragma unroll 1
    for (int k0 = 0; k0 < 128; k0 += 8) {
        unsigned a0 = As[(wm16 + grp)     * LM_ASTRIDE + k0 + tig];
        unsigned a1 = As[(wm16 + grp + 8) * LM_ASTRIDE + k0 + tig];
        unsigned a2 = As[(wm16 + grp)     * LM_ASTRIDE + k0 + 4 + tig];
        unsigned a3 = As[(wm16 + grp + 8) * LM_ASTRIDE + k0 + 4 + tig];
#pragma unroll
        for (int fn = 0; fn < 16; ++fn) {
            unsigned b0 = Bs[(k0 + tig)     * LM_BSTRIDE + fn * 8 + grp];
            unsigned b1 = Bs[(k0 + 4 + tig) * LM_BSTRIDE + fn * 8 + grp];
            mma_tf32(c[fn], a0, a1, a2, a3, b0, b1);
        }
    }

    // epilogue
    int r0a = row0 + wm16 + grp;
#pragma unroll
    for (int fn = 0; fn < 16; ++fn) {
        int colb = col0 + fn * 8 + 2 * tig;
        if (colb < Vv) {
            float2 bb = *(const float2*)(bf + colb);
            float2 w0, w1;
            w0.x = c[fn][0] + bb.x; w0.y = c[fn][1] + bb.y;
            w1.x = c[fn][2] + bb.x; w1.y = c[fn][3] + bb.y;
            *(float2*)(out + (size_t)r0a * Vv + colb)       = w0;
            *(float2*)(out + (size_t)(r0a + 8) * Vv + colb) = w1;
        }
    }
}

// ---------------- launcher ----------------
extern "C" void kernel_launch(void* const* d_in, const int* in_sizes, int n_in,
                              void* d_out, int out_size) {
    const int*   idx  = (const int*)  d_in[0];
    const float* tok  = (const float*)d_in[1];
    const float* pos  = (const float*)d_in[2];
    const float* Wk   = (const float*)d_in[3];
    const float* bk   = (const float*)d_in[4];
    const float* Wv   = (const float*)d_in[5];
    const float* bv   = (const float*)d_in[6];
    const float* Wo   = (const float*)d_in[7];
    const float* bo   = (const float*)d_in[8];
    const float* W1   = (const float*)d_in[9];
    const float* b1   = (const float*)d_in[10];
    const float* W2   = (const float*)d_in[11];
    const float* b2   = (const float*)d_in[12];
    const float* ln1g = (const float*)d_in[13];
    const float* ln1b = (const float*)d_in[14];
    const float* ln2g = (const float*)d_in[15];
    const float* ln2b = (const float*)d_in[16];
    const float* lnfg = (const float*)d_in[17];
    const float* lnfb = (const float*)d_in[18];
    const float* Wf   = (const float*)d_in[19];
    const float* bf   = (const float*)d_in[20];
    float* out = (float*)d_out;

    static int attr_done = 0;
    if (!attr_done) {
        cudaFuncSetAttribute(attn_kernel,
                             cudaFuncAttributeMaxDynamicSharedMemorySize, ATT_SMEM);
        cudaFuncSetAttribute(lmhead_kernel,
                             cudaFuncAttributeMaxDynamicSharedMemorySize, LM_SMEM);
        attr_done = 1;
    }

    // Wf -> tf32 (independent; overlaps nothing but cheap)
    cvt_wf_kernel<<<6250, 256>>>(Wf);

    embed_kernel<<<Rr, 128>>>(idx, tok, pos);

    for (int l = 0; l < Ll; ++l) {
        ln_kernel<<<Rr, 128>>>(ln1g + l * Ee, ln1b + l * Ee, 1);
        kv_kernel<<<Rr / KV_RPB, 128>>>(Wk + (size_t)l * Hh * Ee * HSs,
                                        bk + (size_t)l * Hh * HSs,
                                        Wv + (size_t)l * Hh * Ee * HSs,
                                        bv + (size_t)l * Hh * HSs);
        attn_kernel<<<Bb * Hh, 256, ATT_SMEM>>>();
        proj_kernel<<<Rr / 8, 128>>>(Wo + (size_t)l * Ee * Ee, bo + (size_t)l * Ee);
        ln_kernel<<<Rr, 128>>>(ln2g + l * Ee, ln2b + l * Ee, 1);
        ffn1_kernel<<<Rr / 8, 256>>>(W1 + (size_t)l * Ee * FFf, b1 + (size_t)l * FFf);
        ffn2_kernel<<<Rr / 8, 128>>>(W2 + (size_t)l * FFf * Ee, b2 + (size_t)l * Ee);
    }

    ln_kernel<<<Rr, 128>>>(lnfg, lnfb, 0);
    cvt_h_kernel<<<512, 256>>>();

    dim3 grid((Vv + 127) / 128, Rr / 128);
    lmhead_kernel<<<grid, 256, LM_SMEM>>>(bf, out);
}

// round 14
// speedup vs baseline: 1.6892x; 1.0217x over previous
#include <cuda_runtime.h>
#include <cuda_bf16.h>
#include <cstddef>

// Problem constants
#define Vv   50000
#define Ee   128
#define Cc   128
#define Hh   4
#define Ll   4
#define HSs  32
#define FFf  512
#define Bb   32
#define Rr   (Bb * Cc)        // 4096 rows
#define SCALE 0.08838834764831845f   // 1/sqrt(128)

// ---------------- scratch (static device globals; no allocation) ----------------
__device__ float g_x[Rr * Ee];         // residual stream
__device__ float g_h[Rr * Ee];         // LN output
__device__ float g_k[Rr * Ee];         // (B,H,C,HS)
__device__ float g_v[Rr * Ee];         // (B,H,C,HS)
__device__ float g_att[Rr * Ee];       // attention out in (B,C,E)
__device__ float g_u[Rr * FFf];        // FFN intermediate (post-relu)
__device__ unsigned g_ha[Rr * Ee];     // tf32 final-LN activations

// ---------------- tf32 convert helper ----------------
__device__ __forceinline__ unsigned f2tf32(float f) {
    unsigned o;
    asm("cvt.rna.tf32.f32 %0, %1;" : "=r"(o) : "f"(f));
    return o;
}

// ---------------- embedding gather ----------------
__global__ void embed_kernel(const int* __restrict__ idx,
                             const float* __restrict__ te,
                             const float* __restrict__ pe) {
    int r = blockIdx.x;
    int t = threadIdx.x;
    int tok = idx[r];
    size_t off = (size_t)tok * Ee + t;
    g_x[r * Ee + t] = te[off] + pe[off];
}

// ---------------- LayerNorm: warp-per-row, 4 rows per CTA ----------------
__global__ void ln_kernel(const float* __restrict__ gg,
                          const float* __restrict__ bb,
                          int unbiased) {
    int r = blockIdx.x * 4 + (threadIdx.x >> 5);
    int lane = threadIdx.x & 31;
    float4 v = ((const float4*)(g_x + (size_t)r * Ee))[lane];
    float s = v.x + v.y + v.z + v.w;
#pragma unroll
    for (int o = 16; o; o >>= 1) s += __shfl_xor_sync(0xffffffffu, s, o);
    float mean = s * (1.0f / Ee);
    float4 d = make_float4(v.x - mean, v.y - mean, v.z - mean, v.w - mean);
    float q = d.x * d.x + d.y * d.y + d.z * d.z + d.w * d.w;
#pragma unroll
    for (int o = 16; o; o >>= 1) q += __shfl_xor_sync(0xffffffffu, q, o);
    float var = q * (unbiased ? (1.0f / (Ee - 1)) : (1.0f / Ee));
    float is = rsqrtf(var + 1e-5f);
    float4 G = ((const float4*)gg)[lane];
    float4 Bc = ((const float4*)bb)[lane];
    float4 o4;
    o4.x = d.x * is * G.x + Bc.x;
    o4.y = d.y * is * G.y + Bc.y;
    o4.z = d.z * is * G.z + Bc.z;
    o4.w = d.w * is * G.w + Bc.w;
    ((float4*)(g_h + (size_t)r * Ee))[lane] = o4;
}

// ---------------- final LayerNorm (biased) -> tf32 activations ----------------
__global__ void lnf_kernel(const float* __restrict__ gg,
                           const float* __restrict__ bb) {
    int r = blockIdx.x * 4 + (threadIdx.x >> 5);
    int lane = threadIdx.x & 31;
    float4 v = ((const float4*)(g_x + (size_t)r * Ee))[lane];
    float s = v.x + v.y + v.z + v.w;
#pragma unroll
    for (int o = 16; o; o >>= 1) s += __shfl_xor_sync(0xffffffffu, s, o);
    float mean = s * (1.0f / Ee);
    float4 d = make_float4(v.x - mean, v.y - mean, v.z - mean, v.w - mean);
    float q = d.x * d.x + d.y * d.y + d.z * d.z + d.w * d.w;
#pragma unroll
    for (int o = 16; o; o >>= 1) q += __shfl_xor_sync(0xffffffffu, q, o);
    float var = q * (1.0f / Ee);
    float is = rsqrtf(var + 1e-5f);
    float4 G = ((const float4*)gg)[lane];
    float4 Bc = ((const float4*)bb)[lane];
    uint4 o4;
    o4.x = f2tf32(d.x * is * G.x + Bc.x);
    o4.y = f2tf32(d.y * is * G.y + Bc.y);
    o4.z = f2tf32(d.z * is * G.z + Bc.z);
    o4.w = f2tf32(d.w * is * G.w + Bc.w);
    ((uint4*)(g_ha + (size_t)r * Ee))[lane] = o4;
}

// ---------------- K/V projection: 4 rows/CTA for occupancy ----------------
#define KV_RPB 4
__global__ void kv_kernel(const float* __restrict__ Wk, const float* __restrict__ bk,
                          const float* __restrict__ Wv, const float* __restrict__ bv) {
    __shared__ float sh[KV_RPB * Ee];
    int r0 = blockIdx.x * KV_RPB;
    int t = threadIdx.x;   // 128
#pragma unroll
    for (int i = 0; i < KV_RPB; ++i) sh[i * Ee + t] = g_h[(r0 + i) * Ee + t];
    __syncthreads();

    int hd = t >> 5, f = t & 31;
    float ak[KV_RPB], av[KV_RPB];
#pragma unroll
    for (int i = 0; i < KV_RPB; ++i) { ak[i] = 0.f; av[i] = 0.f; }

    const float* wkp = Wk + (size_t)hd * Ee * HSs + f;
    const float* wvp = Wv + (size_t)hd * Ee * HSs + f;
#pragma unroll 4
    for (int e = 0; e < Ee; ++e) {
        float wk = wkp[e * HSs];
        float wv = wvp[e * HSs];
#pragma unroll
        for (int i = 0; i < KV_RPB; ++i) {
            float hv = sh[i * Ee + e];
            ak[i] += hv * wk;
            av[i] += hv * wv;
        }
    }
    float bkv = bk[hd * HSs + f];
    float bvv = bv[hd * HSs + f];
#pragma unroll
    for (int i = 0; i < KV_RPB; ++i) {
        int r = r0 + i;
        int bb = r >> 7, cc = r & 127;
        size_t o = (((size_t)bb * Hh + hd) * Cc + cc) * HSs + f;
        g_k[o] = ak[i] + bkv;
        g_v[o] = av[i] + bvv;
    }
}

// ---------------- attention (two-pass, smem score tile) ----------------
#define ATT_SSTRIDE 133
#define ATT_SMEM (Cc*HSs*4 + Cc*HSs*4 + Cc*ATT_SSTRIDE*4)
__global__ void attn_kernel() {
    extern __shared__ float dsm[];
    float* Kt = dsm;                         // [128][32]
    float* Vt = dsm + Cc * HSs;              // [128][32]
    float* S  = dsm + 2 * Cc * HSs;          // [128][133]
    __shared__ float Sm[2][Cc];
    __shared__ float Zp[2][Cc];

    int bh = blockIdx.x;
    int b = bh >> 2, h = bh & 3;
    int t = threadIdx.x;          // 0..255
    int c = t & 127;
    int half = t >> 7;

    const float4* kb = (const float4*)(g_k + (size_t)bh * Cc * HSs);
    const float4* vb = (const float4*)(g_v + (size_t)bh * Cc * HSs);
#pragma unroll
    for (int i = 0; i < 4; ++i) {
        ((float4*)Kt)[t + i * 256] = kb[t + i * 256];
        ((float4*)Vt)[t + i * 256] = vb[t + i * 256];
    }
    __syncthreads();

    float4 kr[8];
    const float4* krow = (const float4*)(Kt + c * HSs);
#pragma unroll
    for (int q = 0; q < 8; ++q) kr[q] = krow[q];

    int c2base = half * 64;
    float mh = -1e30f;
    const float4* K4 = (const float4*)Kt;
#pragma unroll 4
    for (int j = 0; j < 64; ++j) {
        int c2 = c2base + j;
        float s0 = 0.f, s1 = 0.f, s2 = 0.f, s3 = 0.f;
#pragma unroll
        for (int q = 0; q < 8; q += 2) {
            float4 a = K4[c2 * 8 + q];
            float4 bq = K4[c2 * 8 + q + 1];
            s0 += kr[q].x * a.x;      s1 += kr[q].y * a.y;
            s2 += kr[q].z * a.z;      s3 += kr[q].w * a.w;
            s0 += kr[q + 1].x * bq.x; s1 += kr[q + 1].y * bq.y;
            s2 += kr[q + 1].z * bq.z; s3 += kr[q + 1].w * bq.w;
        }
        float s = ((s0 + s1) + (s2 + s3)) * SCALE;
        float sv = (c2 <= c) ? s : -INFINITY;
        S[c * ATT_SSTRIDE + c2] = sv;
        mh = fmaxf(mh, sv);
    }
    Sm[half][c] = mh;
    __syncthreads();
    float m = fmaxf(Sm[0][c], Sm[1][c]);

    float z = 0.f;
#pragma unroll 4
    for (int j = 0; j < 64; ++j) {
        int c2 = c2base + j;
        float e = __expf(S[c * ATT_SSTRIDE + c2] - m);
        S[c * ATT_SSTRIDE + c2] = e;
        z += e;
    }
    Zp[half][c] = z;
    __syncthreads();
    float inv = 1.0f / (Zp[0][c] + Zp[1][c]);

    int fb = half * 16;
    float4 a0 = {0,0,0,0}, a1 = {0,0,0,0}, a2 = {0,0,0,0}, a3 = {0,0,0,0};
    const float4* V4 = (const float4*)Vt;
#pragma unroll 4
    for (int c2 = 0; c2 < Cc; ++c2) {
        float p = S[c * ATT_SSTRIDE + c2];
        const float4* vr = V4 + c2 * 8 + (fb >> 2);
        float4 v0 = vr[0], v1 = vr[1], v2 = vr[2], v3 = vr[3];
        a0.x += p * v0.x; a0.y += p * v0.y; a0.z += p * v0.z; a0.w += p * v0.w;
        a1.x += p * v1.x; a1.y += p * v1.y; a1.z += p * v1.z; a1.w += p * v1.w;
        a2.x += p * v2.x; a2.y += p * v2.y; a2.z += p * v2.z; a2.w += p * v2.w;
        a3.x += p * v3.x; a3.y += p * v3.y; a3.z += p * v3.z; a3.w += p * v3.w;
    }
    float* orow = g_att + ((size_t)(b * Cc + c)) * Ee + h * HSs + fb;
    a0.x *= inv; a0.y *= inv; a0.z *= inv; a0.w *= inv;
    a1.x *= inv; a1.y *= inv; a1.z *= inv; a1.w *= inv;
    a2.x *= inv; a2.y *= inv; a2.z *= inv; a2.w *= inv;
    a3.x *= inv; a3.y *= inv; a3.z *= inv; a3.w *= inv;
    ((float4*)orow)[0] = a0; ((float4*)orow)[1] = a1;
    ((float4*)orow)[2] = a2; ((float4*)orow)[3] = a3;
}

// ---------------- output projection + residual: 4 rows/CTA ----------------
__global__ void proj_kernel(const float* __restrict__ Wo, const float* __restrict__ bo) {
    __shared__ float sa[4 * Ee];
    int r0 = blockIdx.x * 4;
    int t = threadIdx.x;  // 128
#pragma unroll
    for (int i = 0; i < 4; ++i) sa[i * Ee + t] = g_att[(r0 + i) * Ee + t];
    __syncthreads();
    float acc[4];
#pragma unroll
    for (int i = 0; i < 4; ++i) acc[i] = 0.f;
#pragma unroll 4
    for (int e = 0; e < Ee; ++e) {
        float w = Wo[e * Ee + t];
#pragma unroll
        for (int i = 0; i < 4; ++i) acc[i] += sa[i * Ee + e] * w;
    }
    float bb = bo[t];
#pragma unroll
    for (int i = 0; i < 4; ++i) g_x[(r0 + i) * Ee + t] += acc[i] + bb;
}

// ---------------- FFN1: 8 rows/CTA, 256 threads ----------------
__global__ void ffn1_kernel(const float* __restrict__ W1, const float* __restrict__ b1) {
    __shared__ float sh[8 * Ee];
    int r0 = blockIdx.x * 8;
    int t = threadIdx.x;  // 256
    for (int i = t; i < 8 * Ee; i += 256) sh[i] = g_h[r0 * Ee + i];
    __syncthreads();
    float acc0[8], acc1[8];
#pragma unroll
    for (int i = 0; i < 8; ++i) { acc0[i] = 0.f; acc1[i] = 0.f; }
#pragma unroll 4
    for (int e = 0; e < Ee; ++e) {
        float w0 = W1[e * FFf + t];
        float w1 = W1[e * FFf + t + 256];
#pragma unroll
        for (int i = 0; i < 8; ++i) {
            float hv = sh[i * Ee + e];
            acc0[i] += hv * w0;
            acc1[i] += hv * w1;
        }
    }
    float bb0 = b1[t], bb1 = b1[t + 256];
#pragma unroll
    for (int i = 0; i < 8; ++i) {
        g_u[(r0 + i) * FFf + t]       = fmaxf(acc0[i] + bb0, 0.f);
        g_u[(r0 + i) * FFf + t + 256] = fmaxf(acc1[i] + bb1, 0.f);
    }
}

// ---------------- FFN2 + residual: 4 rows/CTA ----------------
__global__ void ffn2_kernel(const float* __restrict__ W2, const float* __restrict__ b2) {
    __shared__ float su[4 * FFf];   // 8 KB
    int r0 = blockIdx.x * 4;
    int t = threadIdx.x;  // 128
    for (int i = t; i < 4 * FFf; i += 128) su[i] = g_u[r0 * FFf + i];
    __syncthreads();
    float acc[4];
#pragma unroll
    for (int i = 0; i < 4; ++i) acc[i] = 0.f;
#pragma unroll 4
    for (int jf = 0; jf < FFf; ++jf) {
        float w = W2[jf * Ee + t];
#pragma unroll
        for (int i = 0; i < 4; ++i) acc[i] += su[i * FFf + jf] * w;
    }
    float bb = b2[t];
#pragma unroll
    for (int i = 0; i < 4; ++i) g_x[(r0 + i) * Ee + t] += acc[i] + bb;
}

// ---------------- LM head: tf32 mma.sync, BM=256 BN=128 K=128, 512 threads ----------------
// smem: Bs[128][136] u32 = 69632 bytes. A frags straight from g_ha (L1/L2).
#define LM_BSTRIDE 136
#define LM_SMEM (128 * LM_BSTRIDE * 4)

__device__ __forceinline__ void mma_tf32(float c[4],
                                         unsigned a0, unsigned a1, unsigned a2, unsigned a3,
                                         unsigned b0, unsigned b1) {
    asm volatile(
        "mma.sync.aligned.m16n8k8.row.col.f32.tf32.tf32.f32 "
        "{%0,%1,%2,%3}, {%4,%5,%6,%7}, {%8,%9}, {%0,%1,%2,%3};\n"
        : "+f"(c[0]), "+f"(c[1]), "+f"(c[2]), "+f"(c[3])
        : "r"(a0), "r"(a1), "r"(a2), "r"(a3), "r"(b0), "r"(b1));
}

__global__ __launch_bounds__(512, 1)
void lmhead_kernel(const float* __restrict__ Wf,
                   const float* __restrict__ bf,
                   float* __restrict__ out) {
    extern __shared__ unsigned Bs[];          // [128][136]
    int tid  = threadIdx.x;
    int row0 = blockIdx.y * 256;
    int col0 = blockIdx.x * 128;

    // load + convert B tile (128 k-rows x 128 cols), fp32 -> tf32
#pragma unroll
    for (int i = 0; i < 8; ++i) {
        int id4 = tid + i * 512;              // 0..4095
        int k   = id4 >> 5;
        int c4  = (id4 & 31) << 2;
        int col = col0 + c4;
        float4 bv;
        if (col + 3 < Vv) {
            bv = *(const float4*)(Wf + (size_t)k * Vv + col);
        } else {
            bv.x = (col     < Vv) ? Wf[(size_t)k * Vv + col]     : 0.f;
            bv.y = (col + 1 < Vv) ? Wf[(size_t)k * Vv + col + 1] : 0.f;
            bv.z = (col + 2 < Vv) ? Wf[(size_t)k * Vv + col + 2] : 0.f;
            bv.w = (col + 3 < Vv) ? Wf[(size_t)k * Vv + col + 3] : 0.f;
        }
        uint4 o;
        o.x = f2tf32(bv.x); o.y = f2tf32(bv.y); o.z = f2tf32(bv.z); o.w = f2tf32(bv.w);
        *(uint4*)(&Bs[k * LM_BSTRIDE + c4]) = o;
    }
    __syncthreads();

    int w    = tid >> 5;
    int lane = tid & 31;
    int grp  = lane >> 2;     // 0..7
    int tig  = lane & 3;      // 0..3
    int n0   = (w & 1) * 64;
    int m0   = (w >> 1) * 32;

    const unsigned* A0 = g_ha + (size_t)(row0 + m0 + grp) * Ee;

    float c[2][8][4];
#pragma unroll
    for (int s = 0; s < 2; ++s)
#pragma unroll
        for (int fn = 0; fn < 8; ++fn)
#pragma unroll
            for (int j = 0; j < 4; ++j) c[s][fn][j] = 0.f;

    unsigned a[8];
    a[0] = A0[tig];                 a[1] = A0[8 * Ee + tig];
    a[2] = A0[4 + tig];             a[3] = A0[8 * Ee + 4 + tig];
    a[4] = A0[16 * Ee + tig];       a[5] = A0[24 * Ee + tig];
    a[6] = A0[16 * Ee + 4 + tig];   a[7] = A0[24 * Ee + 4 + tig];

#pragma unroll 1
    for (int k0 = 0; k0 < 128; k0 += 8) {
        unsigned an[8] = {0, 0, 0, 0, 0, 0, 0, 0};
        if (k0 < 120) {
            int kb = k0 + 8;
            an[0] = A0[kb + tig];                an[1] = A0[8 * Ee + kb + tig];
            an[2] = A0[kb + 4 + tig];            an[3] = A0[8 * Ee + kb + 4 + tig];
            an[4] = A0[16 * Ee + kb + tig];      an[5] = A0[24 * Ee + kb + tig];
            an[6] = A0[16 * Ee + kb + 4 + tig];  an[7] = A0[24 * Ee + kb + 4 + tig];
        }
#pragma unroll
        for (int fn = 0; fn < 8; ++fn) {
            unsigned b0 = Bs[(k0 + tig)     * LM_BSTRIDE + n0 + fn * 8 + grp];
            unsigned b1 = Bs[(k0 + 4 + tig) * LM_BSTRIDE + n0 + fn * 8 + grp];
            mma_tf32(c[0][fn], a[0], a[1], a[2], a[3], b0, b1);
            mma_tf32(c[1][fn], a[4], a[5], a[6], a[7], b0, b1);
        }
#pragma unroll
        for (int j = 0; j < 8; ++j) a[j] = an[j];
    }

    // epilogue
#pragma unroll
    for (int s = 0; s < 2; ++s) {
        int ra = row0 + m0 + s * 16 + grp;
#pragma unroll
        for (int fn = 0; fn < 8; ++fn) {
            int colb = col0 + n0 + fn * 8 + 2 * tig;
            if (colb < Vv) {
                float2 bb = *(const float2*)(bf + colb);
                float2 w0, w1;
                w0.x = c[s][fn][0] + bb.x; w0.y = c[s][fn][1] + bb.y;
                w1.x = c[s][fn][2] + bb.x; w1.y = c[s][fn][3] + bb.y;
                *(float2*)(out + (size_t)ra * Vv + colb)       = w0;
                *(float2*)(out + (size_t)(ra + 8) * Vv + colb) = w1;
            }
        }
    }
}

// ---------------- launcher ----------------
extern "C" void kernel_launch(void* const* d_in, const int* in_sizes, int n_in,
                              void* d_out, int out_size) {
    const int*   idx  = (const int*)  d_in[0];
    const float* tok  = (const float*)d_in[1];
    const float* pos  = (const float*)d_in[2];
    const float* Wk   = (const float*)d_in[3];
    const float* bk   = (const float*)d_in[4];
    const float* Wv   = (const float*)d_in[5];
    const float* bv   = (const float*)d_in[6];
    const float* Wo   = (const float*)d_in[7];
    const float* bo   = (const float*)d_in[8];
    const float* W1   = (const float*)d_in[9];
    const float* b1   = (const float*)d_in[10];
    const float* W2   = (const float*)d_in[11];
    const float* b2   = (const float*)d_in[12];
    const float* ln1g = (const float*)d_in[13];
    const float* ln1b = (const float*)d_in[14];
    const float* ln2g = (const float*)d_in[15];
    const float* ln2b = (const float*)d_in[16];
    const float* lnfg = (const float*)d_in[17];
    const float* lnfb = (const float*)d_in[18];
    const float* Wf   = (const float*)d_in[19];
    const float* bf   = (const float*)d_in[20];
    float* out = (float*)d_out;

    static int attr_done = 0;
    if (!attr_done) {
        cudaFuncSetAttribute(attn_kernel,
                             cudaFuncAttributeMaxDynamicSharedMemorySize, ATT_SMEM);
        cudaFuncSetAttribute(lmhead_kernel,
                             cudaFuncAttributeMaxDynamicSharedMemorySize, LM_SMEM);
        attr_done = 1;
    }

    embed_kernel<<<Rr, 128>>>(idx, tok, pos);

    for (int l = 0; l < Ll; ++l) {
        ln_kernel<<<Rr / 4, 128>>>(ln1g + l * Ee, ln1b + l * Ee, 1);
        kv_kernel<<<Rr / KV_RPB, 128>>>(Wk + (size_t)l * Hh * Ee * HSs,
                                        bk + (size_t)l * Hh * HSs,
                                        Wv + (size_t)l * Hh * Ee * HSs,
                                        bv + (size_t)l * Hh * HSs);
        attn_kernel<<<Bb * Hh, 256, ATT_SMEM>>>();
        proj_kernel<<<Rr / 4, 128>>>(Wo + (size_t)l * Ee * Ee, bo + (size_t)l * Ee);
        ln_kernel<<<Rr / 4, 128>>>(ln2g + l * Ee, ln2b + l * Ee, 1);
        ffn1_kernel<<<Rr / 8, 256>>>(W1 + (size_t)l * Ee * FFf, b1 + (size_t)l * FFf);
        ffn2_kernel<<<Rr / 4, 128>>>(W2 + (size_t)l * FFf * Ee, b2 + (size_t)l * Ee);
    }

    lnf_kernel<<<Rr / 4, 128>>>(lnfg, lnfb);

    dim3 grid((Vv + 127) / 128, Rr / 256);
    lmhead_kernel<<<grid, 512, LM_SMEM>>>(Wf, bf, out);
}

// round 15
// speedup vs baseline: 2.4555x; 1.4537x over previous
#include <cuda_runtime.h>
#include <cuda_bf16.h>
#include <cstddef>

// Problem constants
#define Vv   50000
#define Ee   128
#define Cc   128
#define Hh   4
#define Ll   4
#define HSs  32
#define FFf  512
#define Bb   32
#define Rr   (Bb * Cc)        // 4096 rows
#define SCALE 0.08838834764831845f   // 1/sqrt(128)

// ---------------- scratch (static device globals; no allocation) ----------------
__device__ float g_x[Rr * Ee];         // residual stream
__device__ float g_h[Rr * Ee];         // LN output
__device__ float g_k[Rr * Ee];         // (B,H,C,HS)
__device__ float g_v[Rr * Ee];         // (B,H,C,HS)
__device__ float g_att[Rr * Ee];       // attention out in (B,C,E)
__device__ float g_u[Rr * FFf];        // FFN intermediate (post-relu)
__device__ unsigned g_ha[Rr * Ee];     // tf32 final-LN activations

// ---------------- tf32 helpers ----------------
__device__ __forceinline__ unsigned f2tf32(float f) {
    unsigned o;
    asm("cvt.rna.tf32.f32 %0, %1;" : "=r"(o) : "f"(f));
    return o;
}

__device__ __forceinline__ void mma_tf32(float c[4],
                                         unsigned a0, unsigned a1, unsigned a2, unsigned a3,
                                         unsigned b0, unsigned b1) {
    asm volatile(
        "mma.sync.aligned.m16n8k8.row.col.f32.tf32.tf32.f32 "
        "{%0,%1,%2,%3}, {%4,%5,%6,%7}, {%8,%9}, {%0,%1,%2,%3};\n"
        : "+f"(c[0]), "+f"(c[1]), "+f"(c[2]), "+f"(c[3])
        : "r"(a0), "r"(a1), "r"(a2), "r"(a3), "r"(b0), "r"(b1));
}

// ---------------- generic tf32 GEMM tile machinery (BM=64, BN=64, Kc=128, 128 thr) ----
#define GA_STR 132
#define GB_STR 72
#define GEMM_SMEM ((64 * GA_STR + 128 * GB_STR) * 4)   // 70656 bytes

__device__ __forceinline__ void load_A_tile(unsigned* As, const float* A,
                                            int row0, int ldA, int koff) {
    int tid = threadIdx.x;
#pragma unroll
    for (int i = 0; i < 16; ++i) {
        int id4 = tid + i * 128;          // 0..2047
        int m   = id4 >> 5;               // 0..63
        int e4  = (id4 & 31) << 2;        // 0..124
        float4 v = *(const float4*)(A + (size_t)(row0 + m) * ldA + koff + e4);
        uint4 o;
        o.x = f2tf32(v.x); o.y = f2tf32(v.y); o.z = f2tf32(v.z); o.w = f2tf32(v.w);
        *(uint4*)(As + m * GA_STR + e4) = o;
    }
}

__device__ __forceinline__ void load_B_tile(unsigned* Bs, const float* B,
                                            int ldB, int n0, int krow0) {
    int tid = threadIdx.x;
#pragma unroll
    for (int i = 0; i < 16; ++i) {
        int id4 = tid + i * 128;          // 0..2047
        int k   = id4 >> 4;               // 0..127
        int n4  = (id4 & 15) << 2;        // 0..60
        float4 v = *(const float4*)(B + (size_t)(krow0 + k) * ldB + n0 + n4);
        uint4 o;
        o.x = f2tf32(v.x); o.y = f2tf32(v.y); o.z = f2tf32(v.z); o.w = f2tf32(v.w);
        *(uint4*)(Bs + k * GB_STR + n4) = o;
    }
}

__device__ __forceinline__ void gemm_tile_compute(const unsigned* As, const unsigned* Bs,
                                                  int m0, int grp, int tig,
                                                  float c[8][4]) {
#pragma unroll 4
    for (int k0 = 0; k0 < 128; k0 += 8) {
        unsigned a0 = As[(m0 + grp)     * GA_STR + k0 + tig];
        unsigned a1 = As[(m0 + grp + 8) * GA_STR + k0 + tig];
        unsigned a2 = As[(m0 + grp)     * GA_STR + k0 + 4 + tig];
        unsigned a3 = As[(m0 + grp + 8) * GA_STR + k0 + 4 + tig];
#pragma unroll
        for (int fn = 0; fn < 8; ++fn) {
            unsigned b0 = Bs[(k0 + tig)     * GB_STR + fn * 8 + grp];
            unsigned b1 = Bs[(k0 + 4 + tig) * GB_STR + fn * 8 + grp];
            mma_tf32(c[fn], a0, a1, a2, a3, b0, b1);
        }
    }
}

// ---------------- embedding gather ----------------
__global__ void embed_kernel(const int* __restrict__ idx,
                             const float* __restrict__ te,
                             const float* __restrict__ pe) {
    int r = blockIdx.x;
    int t = threadIdx.x;
    int tok = idx[r];
    size_t off = (size_t)tok * Ee + t;
    g_x[r * Ee + t] = te[off] + pe[off];
}

// ---------------- LayerNorm: warp-per-row, 4 rows per CTA ----------------
__global__ void ln_kernel(const float* __restrict__ gg,
                          const float* __restrict__ bb,
                          int unbiased) {
    int r = blockIdx.x * 4 + (threadIdx.x >> 5);
    int lane = threadIdx.x & 31;
    float4 v = ((const float4*)(g_x + (size_t)r * Ee))[lane];
    float s = v.x + v.y + v.z + v.w;
#pragma unroll
    for (int o = 16; o; o >>= 1) s += __shfl_xor_sync(0xffffffffu, s, o);
    float mean = s * (1.0f / Ee);
    float4 d = make_float4(v.x - mean, v.y - mean, v.z - mean, v.w - mean);
    float q = d.x * d.x + d.y * d.y + d.z * d.z + d.w * d.w;
#pragma unroll
    for (int o = 16; o; o >>= 1) q += __shfl_xor_sync(0xffffffffu, q, o);
    float var = q * (unbiased ? (1.0f / (Ee - 1)) : (1.0f / Ee));
    float is = rsqrtf(var + 1e-5f);
    float4 G = ((const float4*)gg)[lane];
    float4 Bc = ((const float4*)bb)[lane];
    float4 o4;
    o4.x = d.x * is * G.x + Bc.x;
    o4.y = d.y * is * G.y + Bc.y;
    o4.z = d.z * is * G.z + Bc.z;
    o4.w = d.w * is * G.w + Bc.w;
    ((float4*)(g_h + (size_t)r * Ee))[lane] = o4;
}

// ---------------- final LayerNorm (biased) -> tf32 activations ----------------
__global__ void lnf_kernel(const float* __restrict__ gg,
                           const float* __restrict__ bb) {
    int r = blockIdx.x * 4 + (threadIdx.x >> 5);
    int lane = threadIdx.x & 31;
    float4 v = ((const float4*)(g_x + (size_t)r * Ee))[lane];
    float s = v.x + v.y + v.z + v.w;
#pragma unroll
    for (int o = 16; o; o >>= 1) s += __shfl_xor_sync(0xffffffffu, s, o);
    float mean = s * (1.0f / Ee);
    float4 d = make_float4(v.x - mean, v.y - mean, v.z - mean, v.w - mean);
    float q = d.x * d.x + d.y * d.y + d.z * d.z + d.w * d.w;
#pragma unroll
    for (int o = 16; o; o >>= 1) q += __shfl_xor_sync(0xffffffffu, q, o);
    float var = q * (1.0f / Ee);
    float is = rsqrtf(var + 1e-5f);
    float4 G = ((const float4*)gg)[lane];
    float4 Bc = ((const float4*)bb)[lane];
    uint4 o4;
    o4.x = f2tf32(d.x * is * G.x + Bc.x);
    o4.y = f2tf32(d.y * is * G.y + Bc.y);
    o4.z = f2tf32(d.z * is * G.z + Bc.z);
    o4.w = f2tf32(d.w * is * G.w + Bc.w);
    ((uint4*)(g_ha + (size_t)r * Ee))[lane] = o4;
}

// ---------------- K/V projection via tf32 MMA ----------------
// grid (4, 64): x-blocks over 256 output cols [k:128 | v:128], y over rows.
__global__ __launch_bounds__(128, 3)
void kv_mma_kernel(const float* __restrict__ Wk, const float* __restrict__ bk,
                   const float* __restrict__ Wv, const float* __restrict__ bv) {
    extern __shared__ unsigned sm[];
    unsigned* As = sm;
    unsigned* Bs = sm + 64 * GA_STR;

    int row0  = blockIdx.y * 64;
    int n0g   = blockIdx.x * 64;       // 0,64,128,192
    int isV   = n0g >= 128;
    const float* W    = isV ? Wv : Wk;
    const float* bias = isV ? bv : bk;
    int cbase = n0g & 127;             // 0 or 64

    load_A_tile(As, g_h, row0, Ee, 0);

    int tid = threadIdx.x;
#pragma unroll
    for (int i = 0; i < 16; ++i) {
        int id4 = tid + i * 128;
        int e   = id4 >> 4;            // 0..127
        int j4  = (id4 & 15) << 2;     // 0..60
        int cl  = cbase + j4;
        int h = cl >> 5, f = cl & 31;
        float4 v = *(const float4*)(W + (size_t)h * (Ee * HSs) + e * HSs + f);
        uint4 o;
        o.x = f2tf32(v.x); o.y = f2tf32(v.y); o.z = f2tf32(v.z); o.w = f2tf32(v.w);
        *(uint4*)(Bs + e * GB_STR + j4) = o;
    }
    __syncthreads();

    int w = tid >> 5, lane = tid & 31, grp = lane >> 2, tig = lane & 3;
    int m0 = w * 16;
    float c[8][4];
#pragma unroll
    for (int fn = 0; fn < 8; ++fn)
#pragma unroll
        for (int j = 0; j < 4; ++j) c[fn][j] = 0.f;

    gemm_tile_compute(As, Bs, m0, grp, tig, c);

    float* dst = isV ? g_v : g_k;
#pragma unroll
    for (int fn = 0; fn < 8; ++fn) {
        int cl = cbase + fn * 8 + 2 * tig;
        int h = cl >> 5, f = cl & 31;
        float b0 = bias[h * HSs + f];
        float b1 = bias[h * HSs + f + 1];
        int r = row0 + m0 + grp;
        int bI = r >> 7, cc = r & 127;
        size_t o0 = (((size_t)bI * Hh + h) * Cc + cc) * HSs + f;
        float2 w0 = make_float2(c[fn][0] + b0, c[fn][1] + b1);
        *(float2*)(dst + o0) = w0;
        int r2 = r + 8; bI = r2 >> 7; cc = r2 & 127;
        size_t o1 = (((size_t)bI * Hh + h) * Cc + cc) * HSs + f;
        float2 w1 = make_float2(c[fn][2] + b0, c[fn][3] + b1);
        *(float2*)(dst + o1) = w1;
    }
}

// ---------------- attention (two-pass, smem score tile) ----------------
#define ATT_SSTRIDE 133
#define ATT_SMEM (Cc*HSs*4 + Cc*HSs*4 + Cc*ATT_SSTRIDE*4)
__global__ void attn_kernel() {
    extern __shared__ float dsm[];
    float* Kt = dsm;                         // [128][32]
    float* Vt = dsm + Cc * HSs;              // [128][32]
    float* S  = dsm + 2 * Cc * HSs;          // [128][133]
    __shared__ float Sm[2][Cc];
    __shared__ float Zp[2][Cc];

    int bh = blockIdx.x;
    int b = bh >> 2, h = bh & 3;
    int t = threadIdx.x;          // 0..255
    int c = t & 127;
    int half = t >> 7;

    const float4* kb = (const float4*)(g_k + (size_t)bh * Cc * HSs);
    const float4* vb = (const float4*)(g_v + (size_t)bh * Cc * HSs);
#pragma unroll
    for (int i = 0; i < 4; ++i) {
        ((float4*)Kt)[t + i * 256] = kb[t + i * 256];
        ((float4*)Vt)[t + i * 256] = vb[t + i * 256];
    }
    __syncthreads();

    float4 kr[8];
    const float4* krow = (const float4*)(Kt + c * HSs);
#pragma unroll
    for (int q = 0; q < 8; ++q) kr[q] = krow[q];

    int c2base = half * 64;
    float mh = -1e30f;
    const float4* K4 = (const float4*)Kt;
#pragma unroll 4
    for (int j = 0; j < 64; ++j) {
        int c2 = c2base + j;
        float s0 = 0.f, s1 = 0.f, s2 = 0.f, s3 = 0.f;
#pragma unroll
        for (int q = 0; q < 8; q += 2) {
            float4 a = K4[c2 * 8 + q];
            float4 bq = K4[c2 * 8 + q + 1];
            s0 += kr[q].x * a.x;      s1 += kr[q].y * a.y;
            s2 += kr[q].z * a.z;      s3 += kr[q].w * a.w;
            s0 += kr[q + 1].x * bq.x; s1 += kr[q + 1].y * bq.y;
            s2 += kr[q + 1].z * bq.z; s3 += kr[q + 1].w * bq.w;
        }
        float s = ((s0 + s1) + (s2 + s3)) * SCALE;
        float sv = (c2 <= c) ? s : -INFINITY;
        S[c * ATT_SSTRIDE + c2] = sv;
        mh = fmaxf(mh, sv);
    }
    Sm[half][c] = mh;
    __syncthreads();
    float m = fmaxf(Sm[0][c], Sm[1][c]);

    float z = 0.f;
#pragma unroll 4
    for (int j = 0; j < 64; ++j) {
        int c2 = c2base + j;
        float e = __expf(S[c * ATT_SSTRIDE + c2] - m);
        S[c * ATT_SSTRIDE + c2] = e;
        z += e;
    }
    Zp[half][c] = z;
    __syncthreads();
    float inv = 1.0f / (Zp[0][c] + Zp[1][c]);

    int fb = half * 16;
    float4 a0 = {0,0,0,0}, a1 = {0,0,0,0}, a2 = {0,0,0,0}, a3 = {0,0,0,0};
    const float4* V4 = (const float4*)Vt;
#pragma unroll 4
    for (int c2 = 0; c2 < Cc; ++c2) {
        float p = S[c * ATT_SSTRIDE + c2];
        const float4* vr = V4 + c2 * 8 + (fb >> 2);
        float4 v0 = vr[0], v1 = vr[1], v2 = vr[2], v3 = vr[3];
        a0.x += p * v0.x; a0.y += p * v0.y; a0.z += p * v0.z; a0.w += p * v0.w;
        a1.x += p * v1.x; a1.y += p * v1.y; a1.z += p * v1.z; a1.w += p * v1.w;
        a2.x += p * v2.x; a2.y += p * v2.y; a2.z += p * v2.z; a2.w += p * v2.w;
        a3.x += p * v3.x; a3.y += p * v3.y; a3.z += p * v3.z; a3.w += p * v3.w;
    }
    float* orow = g_att + ((size_t)(b * Cc + c)) * Ee + h * HSs + fb;
    a0.x *= inv; a0.y *= inv; a0.z *= inv; a0.w *= inv;
    a1.x *= inv; a1.y *= inv; a1.z *= inv; a1.w *= inv;
    a2.x *= inv; a2.y *= inv; a2.z *= inv; a2.w *= inv;
    a3.x *= inv; a3.y *= inv; a3.z *= inv; a3.w *= inv;
    ((float4*)orow)[0] = a0; ((float4*)orow)[1] = a1;
    ((float4*)orow)[2] = a2; ((float4*)orow)[3] = a3;
}

// ---------------- output projection + residual via tf32 MMA ----------------
// grid (2, 64)
__global__ __launch_bounds__(128, 3)
void proj_mma_kernel(const float* __restrict__ Wo, const float* __restrict__ bo) {
    extern __shared__ unsigned sm[];
    unsigned* As = sm;
    unsigned* Bs = sm + 64 * GA_STR;

    int row0 = blockIdx.y * 64;
    int n0   = blockIdx.x * 64;

    load_A_tile(As, g_att, row0, Ee, 0);
    load_B_tile(Bs, Wo, Ee, n0, 0);
    __syncthreads();

    int tid = threadIdx.x;
    int w = tid >> 5, lane = tid & 31, grp = lane >> 2, tig = lane & 3;
    int m0 = w * 16;
    float c[8][4];
#pragma unroll
    for (int fn = 0; fn < 8; ++fn)
#pragma unroll
        for (int j = 0; j < 4; ++j) c[fn][j] = 0.f;

    gemm_tile_compute(As, Bs, m0, grp, tig, c);

#pragma unroll
    for (int fn = 0; fn < 8; ++fn) {
        int col = n0 + fn * 8 + 2 * tig;
        float b0 = bo[col], b1 = bo[col + 1];
        int r = row0 + m0 + grp;
        float2* p0 = (float2*)(g_x + (size_t)r * Ee + col);
        float2 x0 = *p0;
        x0.x += c[fn][0] + b0; x0.y += c[fn][1] + b1;
        *p0 = x0;
        float2* p1 = (float2*)(g_x + (size_t)(r + 8) * Ee + col);
        float2 x1 = *p1;
        x1.x += c[fn][2] + b0; x1.y += c[fn][3] + b1;
        *p1 = x1;
    }
}

// ---------------- FFN1 via tf32 MMA: u = relu(h @ W1 + b1). grid (8, 64) ----------------
__global__ __launch_bounds__(128, 3)
void ffn1_mma_kernel(const float* __restrict__ W1, const float* __restrict__ b1) {
    extern __shared__ unsigned sm[];
    unsigned* As = sm;
    unsigned* Bs = sm + 64 * GA_STR;

    int row0 = blockIdx.y * 64;
    int n0   = blockIdx.x * 64;

    load_A_tile(As, g_h, row0, Ee, 0);
    load_B_tile(Bs, W1, FFf, n0, 0);
    __syncthreads();

    int tid = threadIdx.x;
    int w = tid >> 5, lane = tid & 31, grp = lane >> 2, tig = lane & 3;
    int m0 = w * 16;
    float c[8][4];
#pragma unroll
    for (int fn = 0; fn < 8; ++fn)
#pragma unroll
        for (int j = 0; j < 4; ++j) c[fn][j] = 0.f;

    gemm_tile_compute(As, Bs, m0, grp, tig, c);

#pragma unroll
    for (int fn = 0; fn < 8; ++fn) {
        int col = n0 + fn * 8 + 2 * tig;
        float b0 = b1[col], b1v = b1[col + 1];
        int r = row0 + m0 + grp;
        float2 w0 = make_float2(fmaxf(c[fn][0] + b0, 0.f), fmaxf(c[fn][1] + b1v, 0.f));
        *(float2*)(g_u + (size_t)r * FFf + col) = w0;
        float2 w1 = make_float2(fmaxf(c[fn][2] + b0, 0.f), fmaxf(c[fn][3] + b1v, 0.f));
        *(float2*)(g_u + (size_t)(r + 8) * FFf + col) = w1;
    }
}

// ---------------- FFN2 + residual via tf32 MMA: K=512 in 4 chunks. grid (2, 64) ----------
__global__ __launch_bounds__(128, 3)
void ffn2_mma_kernel(const float* __restrict__ W2, const float* __restrict__ b2) {
    extern __shared__ unsigned sm[];
    unsigned* As = sm;
    unsigned* Bs = sm + 64 * GA_STR;

    int row0 = blockIdx.y * 64;
    int n0   = blockIdx.x * 64;

    int tid = threadIdx.x;
    int w = tid >> 5, lane = tid & 31, grp = lane >> 2, tig = lane & 3;
    int m0 = w * 16;
    float c[8][4];
#pragma unroll
    for (int fn = 0; fn < 8; ++fn)
#pragma unroll
        for (int j = 0; j < 4; ++j) c[fn][j] = 0.f;

    for (int chunk = 0; chunk < 4; ++chunk) {
        if (chunk) __syncthreads();
        load_A_tile(As, g_u, row0, FFf, chunk * 128);
        load_B_tile(Bs, W2, Ee, n0, chunk * 128);
        __syncthreads();
        gemm_tile_compute(As, Bs, m0, grp, tig, c);
    }

#pragma unroll
    for (int fn = 0; fn < 8; ++fn) {
        int col = n0 + fn * 8 + 2 * tig;
        float b0 = b2[col], b1 = b2[col + 1];
        int r = row0 + m0 + grp;
        float2* p0 = (float2*)(g_x + (size_t)r * Ee + col);
        float2 x0 = *p0;
        x0.x += c[fn][0] + b0; x0.y += c[fn][1] + b1;
        *p0 = x0;
        float2* p1 = (float2*)(g_x + (size_t)(r + 8) * Ee + col);
        float2 x1 = *p1;
        x1.x += c[fn][2] + b0; x1.y += c[fn][3] + b1;
        *p1 = x1;
    }
}

// ---------------- LM head: tf32 mma, BM=256 BN=128 K=128, 512 threads ----------------
#define LM_BSTRIDE 136
#define LM_SMEM (128 * LM_BSTRIDE * 4)

__global__ __launch_bounds__(512, 1)
void lmhead_kernel(const float* __restrict__ Wf,
                   const float* __restrict__ bf,
                   float* __restrict__ out) {
    extern __shared__ unsigned Bs[];          // [128][136]
    int tid  = threadIdx.x;
    int row0 = blockIdx.y * 256;
    int col0 = blockIdx.x * 128;

#pragma unroll
    for (int i = 0; i < 8; ++i) {
        int id4 = tid + i * 512;              // 0..4095
        int k   = id4 >> 5;
        int c4  = (id4 & 31) << 2;
        int col = col0 + c4;
        float4 bv;
        if (col + 3 < Vv) {
            bv = *(const float4*)(Wf + (size_t)k * Vv + col);
        } else {
            bv.x = (col     < Vv) ? Wf[(size_t)k * Vv + col]     : 0.f;
            bv.y = (col + 1 < Vv) ? Wf[(size_t)k * Vv + col + 1] : 0.f;
            bv.z = (col + 2 < Vv) ? Wf[(size_t)k * Vv + col + 2] : 0.f;
            bv.w = (col + 3 < Vv) ? Wf[(size_t)k * Vv + col + 3] : 0.f;
        }
        uint4 o;
        o.x = f2tf32(bv.x); o.y = f2tf32(bv.y); o.z = f2tf32(bv.z); o.w = f2tf32(bv.w);
        *(uint4*)(&Bs[k * LM_BSTRIDE + c4]) = o;
    }
    __syncthreads();

    int w    = tid >> 5;
    int lane = tid & 31;
    int grp  = lane >> 2;
    int tig  = lane & 3;
    int n0   = (w & 1) * 64;
    int m0   = (w >> 1) * 32;

    const unsigned* A0 = g_ha + (size_t)(row0 + m0 + grp) * Ee;

    float c[2][8][4];
#pragma unroll
    for (int s = 0; s < 2; ++s)
#pragma unroll
        for (int fn = 0; fn < 8; ++fn)
#pragma unroll
            for (int j = 0; j < 4; ++j) c[s][fn][j] = 0.f;

    unsigned a[8];
    a[0] = A0[tig];                 a[1] = A0[8 * Ee + tig];
    a[2] = A0[4 + tig];             a[3] = A0[8 * Ee + 4 + tig];
    a[4] = A0[16 * Ee + tig];       a[5] = A0[24 * Ee + tig];
    a[6] = A0[16 * Ee + 4 + tig];   a[7] = A0[24 * Ee + 4 + tig];

#pragma unroll 1
    for (int k0 = 0; k0 < 128; k0 += 8) {
        unsigned an[8] = {0, 0, 0, 0, 0, 0, 0, 0};
        if (k0 < 120) {
            int kb = k0 + 8;
            an[0] = A0[kb + tig];                an[1] = A0[8 * Ee + kb + tig];
            an[2] = A0[kb + 4 + tig];            an[3] = A0[8 * Ee + kb + 4 + tig];
            an[4] = A0[16 * Ee + kb + tig];      an[5] = A0[24 * Ee + kb + tig];
            an[6] = A0[16 * Ee + kb + 4 + tig];  an[7] = A0[24 * Ee + kb + 4 + tig];
        }
#pragma unroll
        for (int fn = 0; fn < 8; ++fn) {
            unsigned b0 = Bs[(k0 + tig)     * LM_BSTRIDE + n0 + fn * 8 + grp];
            unsigned b1 = Bs[(k0 + 4 + tig) * LM_BSTRIDE + n0 + fn * 8 + grp];
            mma_tf32(c[0][fn], a[0], a[1], a[2], a[3], b0, b1);
            mma_tf32(c[1][fn], a[4], a[5], a[6], a[7], b0, b1);
        }
#pragma unroll
        for (int j = 0; j < 8; ++j) a[j] = an[j];
    }

#pragma unroll
    for (int s = 0; s < 2; ++s) {
        int ra = row0 + m0 + s * 16 + grp;
#pragma unroll
        for (int fn = 0; fn < 8; ++fn) {
            int colb = col0 + n0 + fn * 8 + 2 * tig;
            if (colb < Vv) {
                float2 bb = *(const float2*)(bf + colb);
                float2 w0, w1;
                w0.x = c[s][fn][0] + bb.x; w0.y = c[s][fn][1] + bb.y;
                w1.x = c[s][fn][2] + bb.x; w1.y = c[s][fn][3] + bb.y;
                *(float2*)(out + (size_t)ra * Vv + colb)       = w0;
                *(float2*)(out + (size_t)(ra + 8) * Vv + colb) = w1;
            }
        }
    }
}

// ---------------- launcher ----------------
extern "C" void kernel_launch(void* const* d_in, const int* in_sizes, int n_in,
                              void* d_out, int out_size) {
    const int*   idx  = (const int*)  d_in[0];
    const float* tok  = (const float*)d_in[1];
    const float* pos  = (const float*)d_in[2];
    const float* Wk   = (const float*)d_in[3];
    const float* bk   = (const float*)d_in[4];
    const float* Wv   = (const float*)d_in[5];
    const float* bv   = (const float*)d_in[6];
    const float* Wo   = (const float*)d_in[7];
    const float* bo   = (const float*)d_in[8];
    const float* W1   = (const float*)d_in[9];
    const float* b1   = (const float*)d_in[10];
    const float* W2   = (const float*)d_in[11];
    const float* b2   = (const float*)d_in[12];
    const float* ln1g = (const float*)d_in[13];
    const float* ln1b = (const float*)d_in[14];
    const float* ln2g = (const float*)d_in[15];
    const float* ln2b = (const float*)d_in[16];
    const float* lnfg = (const float*)d_in[17];
    const float* lnfb = (const float*)d_in[18];
    const float* Wf   = (const float*)d_in[19];
    const float* bf   = (const float*)d_in[20];
    float* out = (float*)d_out;

    static int attr_done = 0;
    if (!attr_done) {
        cudaFuncSetAttribute(attn_kernel,
                             cudaFuncAttributeMaxDynamicSharedMemorySize, ATT_SMEM);
        cudaFuncSetAttribute(lmhead_kernel,
                             cudaFuncAttributeMaxDynamicSharedMemorySize, LM_SMEM);
        cudaFuncSetAttribute(kv_mma_kernel,
                             cudaFuncAttributeMaxDynamicSharedMemorySize, GEMM_SMEM);
        cudaFuncSetAttribute(proj_mma_kernel,
                             cudaFuncAttributeMaxDynamicSharedMemorySize, GEMM_SMEM);
        cudaFuncSetAttribute(ffn1_mma_kernel,
                             cudaFuncAttributeMaxDynamicSharedMemorySize, GEMM_SMEM);
        cudaFuncSetAttribute(ffn2_mma_kernel,
                             cudaFuncAttributeMaxDynamicSharedMemorySize, GEMM_SMEM);
        attr_done = 1;
    }

    embed_kernel<<<Rr, 128>>>(idx, tok, pos);

    for (int l = 0; l < Ll; ++l) {
        ln_kernel<<<Rr / 4, 128>>>(ln1g + l * Ee, ln1b + l * Ee, 1);
        kv_mma_kernel<<<dim3(4, 64), 128, GEMM_SMEM>>>(
            Wk + (size_t)l * Hh * Ee * HSs, bk + (size_t)l * Hh * HSs,
            Wv + (size_t)l * Hh * Ee * HSs, bv + (size_t)l * Hh * HSs);
        attn_kernel<<<Bb * Hh, 256, ATT_SMEM>>>();
        proj_mma_kernel<<<dim3(2, 64), 128, GEMM_SMEM>>>(
            Wo + (size_t)l * Ee * Ee, bo + (size_t)l * Ee);
        ln_kernel<<<Rr / 4, 128>>>(ln2g + l * Ee, ln2b + l * Ee, 1);
        ffn1_mma_kernel<<<dim3(8, 64), 128, GEMM_SMEM>>>(
            W1 + (size_t)l * Ee * FFf, b1 + (size_t)l * FFf);
        ffn2_mma_kernel<<<dim3(2, 64), 128, GEMM_SMEM>>>(
            W2 + (size_t)l * FFf * Ee, b2 + (size_t)l * Ee);
    }

    lnf_kernel<<<Rr / 4, 128>>>(lnfg, lnfb);

    dim3 grid((Vv + 127) / 128, Rr / 256);
    lmhead_kernel<<<grid, 512, LM_SMEM>>>(Wf, bf, out);
}

// round 16
// speedup vs baseline: 2.4902x; 1.0141x over previous
#include <cuda_runtime.h>
#include <cuda_bf16.h>
#include <cstddef>

// Problem constants
#define Vv   50000
#define Ee   128
#define Cc   128
#define Hh   4
#define Ll   4
#define HSs  32
#define FFf  512
#define Bb   32
#define Rr   (Bb * Cc)        // 4096 rows
#define SCALE 0.08838834764831845f   // 1/sqrt(128)

// ---------------- scratch (static device globals; no allocation) ----------------
__device__ float g_x[Rr * Ee];         // residual stream
__device__ float g_k[Rr * Ee];         // (B,H,C,HS)
__device__ float g_v[Rr * Ee];         // (B,H,C,HS)
__device__ float g_att[Rr * Ee];       // attention out in (B,C,E)
__device__ float g_u[Rr * FFf];        // FFN intermediate (post-relu)
__device__ unsigned g_ha[Rr * Ee];     // tf32 final-LN activations

// ---------------- tf32 helpers ----------------
__device__ __forceinline__ unsigned f2tf32(float f) {
    unsigned o;
    asm("cvt.rna.tf32.f32 %0, %1;" : "=r"(o) : "f"(f));
    return o;
}

__device__ __forceinline__ void mma_tf32(float c[4],
                                         unsigned a0, unsigned a1, unsigned a2, unsigned a3,
                                         unsigned b0, unsigned b1) {
    asm volatile(
        "mma.sync.aligned.m16n8k8.row.col.f32.tf32.tf32.f32 "
        "{%0,%1,%2,%3}, {%4,%5,%6,%7}, {%8,%9}, {%0,%1,%2,%3};\n"
        : "+f"(c[0]), "+f"(c[1]), "+f"(c[2]), "+f"(c[3])
        : "r"(a0), "r"(a1), "r"(a2), "r"(a3), "r"(b0), "r"(b1));
}

// ---------------- generic tf32 GEMM tile machinery (BM=64, BN=64, Kc=128, 128 thr) ----
#define GA_STR 132
#define GB_STR 72
#define GEMM_SMEM ((64 * GA_STR + 128 * GB_STR) * 4)   // 70656 bytes

__device__ __forceinline__ void load_A_tile(unsigned* As, const float* A,
                                            int row0, int ldA, int koff) {
    int tid = threadIdx.x;
#pragma unroll
    for (int i = 0; i < 16; ++i) {
        int id4 = tid + i * 128;          // 0..2047
        int m   = id4 >> 5;               // 0..63
        int e4  = (id4 & 31) << 2;        // 0..124
        float4 v = *(const float4*)(A + (size_t)(row0 + m) * ldA + koff + e4);
        uint4 o;
        o.x = f2tf32(v.x); o.y = f2tf32(v.y); o.z = f2tf32(v.z); o.w = f2tf32(v.w);
        *(uint4*)(As + m * GA_STR + e4) = o;
    }
}

// LN fused into the A-tile load: each warp holds one full 128-elem row per iter.
// Unbiased variance (ddof=1), matching the reference intra-layer LayerNorm.
__device__ __forceinline__ void load_A_tile_ln(unsigned* As, const float* X, int row0,
                                               const float* __restrict__ gg,
                                               const float* __restrict__ bb) {
    int tid  = threadIdx.x;
    int lane = tid & 31;
    float4 G  = ((const float4*)gg)[lane];
    float4 Bc = ((const float4*)bb)[lane];
#pragma unroll
    for (int i = 0; i < 16; ++i) {
        int id4 = tid + i * 128;
        int m   = id4 >> 5;               // warp-uniform row
        int e4  = lane << 2;
        float4 v = *(const float4*)(X + (size_t)(row0 + m) * Ee + e4);
        float s = v.x + v.y + v.z + v.w;
#pragma unroll
        for (int o = 16; o; o >>= 1) s += __shfl_xor_sync(0xffffffffu, s, o);
        float mean = s * (1.0f / Ee);
        float4 d = make_float4(v.x - mean, v.y - mean, v.z - mean, v.w - mean);
        float q = d.x * d.x + d.y * d.y + d.z * d.z + d.w * d.w;
#pragma unroll
        for (int o = 16; o; o >>= 1) q += __shfl_xor_sync(0xffffffffu, q, o);
        float is = rsqrtf(q * (1.0f / (Ee - 1)) + 1e-5f);
        uint4 o4;
        o4.x = f2tf32(d.x * is * G.x + Bc.x);
        o4.y = f2tf32(d.y * is * G.y + Bc.y);
        o4.z = f2tf32(d.z * is * G.z + Bc.z);
        o4.w = f2tf32(d.w * is * G.w + Bc.w);
        *(uint4*)(As + m * GA_STR + e4) = o4;
    }
}

__device__ __forceinline__ void load_B_tile(unsigned* Bs, const float* B,
                                            int ldB, int n0, int krow0) {
    int tid = threadIdx.x;
#pragma unroll
    for (int i = 0; i < 16; ++i) {
        int id4 = tid + i * 128;          // 0..2047
        int k   = id4 >> 4;               // 0..127
        int n4  = (id4 & 15) << 2;        // 0..60
        float4 v = *(const float4*)(B + (size_t)(krow0 + k) * ldB + n0 + n4);
        uint4 o;
        o.x = f2tf32(v.x); o.y = f2tf32(v.y); o.z = f2tf32(v.z); o.w = f2tf32(v.w);
        *(uint4*)(Bs + k * GB_STR + n4) = o;
    }
}

__device__ __forceinline__ void gemm_tile_compute(const unsigned* As, const unsigned* Bs,
                                                  int m0, int grp, int tig,
                                                  float c[8][4]) {
#pragma unroll 4
    for (int k0 = 0; k0 < 128; k0 += 8) {
        unsigned a0 = As[(m0 + grp)     * GA_STR + k0 + tig];
        unsigned a1 = As[(m0 + grp + 8) * GA_STR + k0 + tig];
        unsigned a2 = As[(m0 + grp)     * GA_STR + k0 + 4 + tig];
        unsigned a3 = As[(m0 + grp + 8) * GA_STR + k0 + 4 + tig];
#pragma unroll
        for (int fn = 0; fn < 8; ++fn) {
            unsigned b0 = Bs[(k0 + tig)     * GB_STR + fn * 8 + grp];
            unsigned b1 = Bs[(k0 + 4 + tig) * GB_STR + fn * 8 + grp];
            mma_tf32(c[fn], a0, a1, a2, a3, b0, b1);
        }
    }
}

// ---------------- embedding gather ----------------
__global__ void embed_kernel(const int* __restrict__ idx,
                             const float* __restrict__ te,
                             const float* __restrict__ pe) {
    int r = blockIdx.x;
    int t = threadIdx.x;
    int tok = idx[r];
    size_t off = (size_t)tok * Ee + t;
    g_x[r * Ee + t] = te[off] + pe[off];
}

// ---------------- final LayerNorm (biased) -> tf32 activations ----------------
__global__ void lnf_kernel(const float* __restrict__ gg,
                           const float* __restrict__ bb) {
    int r = blockIdx.x * 4 + (threadIdx.x >> 5);
    int lane = threadIdx.x & 31;
    float4 v = ((const float4*)(g_x + (size_t)r * Ee))[lane];
    float s = v.x + v.y + v.z + v.w;
#pragma unroll
    for (int o = 16; o; o >>= 1) s += __shfl_xor_sync(0xffffffffu, s, o);
    float mean = s * (1.0f / Ee);
    float4 d = make_float4(v.x - mean, v.y - mean, v.z - mean, v.w - mean);
    float q = d.x * d.x + d.y * d.y + d.z * d.z + d.w * d.w;
#pragma unroll
    for (int o = 16; o; o >>= 1) q += __shfl_xor_sync(0xffffffffu, q, o);
    float var = q * (1.0f / Ee);
    float is = rsqrtf(var + 1e-5f);
    float4 G = ((const float4*)gg)[lane];
    float4 Bc = ((const float4*)bb)[lane];
    uint4 o4;
    o4.x = f2tf32(d.x * is * G.x + Bc.x);
    o4.y = f2tf32(d.y * is * G.y + Bc.y);
    o4.z = f2tf32(d.z * is * G.z + Bc.z);
    o4.w = f2tf32(d.w * is * G.w + Bc.w);
    ((uint4*)(g_ha + (size_t)r * Ee))[lane] = o4;
}

// ---------------- K/V projection via tf32 MMA (LN fused in A-load) ----------------
// grid (4, 64): x-blocks over 256 output cols [k:128 | v:128], y over rows.
__global__ __launch_bounds__(128, 3)
void kv_mma_kernel(const float* __restrict__ Wk, const float* __restrict__ bk,
                   const float* __restrict__ Wv, const float* __restrict__ bv,
                   const float* __restrict__ ln_g, const float* __restrict__ ln_b) {
    extern __shared__ unsigned sm[];
    unsigned* As = sm;
    unsigned* Bs = sm + 64 * GA_STR;

    int row0  = blockIdx.y * 64;
    int n0g   = blockIdx.x * 64;       // 0,64,128,192
    int isV   = n0g >= 128;
    const float* W    = isV ? Wv : Wk;
    const float* bias = isV ? bv : bk;
    int cbase = n0g & 127;             // 0 or 64

    load_A_tile_ln(As, g_x, row0, ln_g, ln_b);

    int tid = threadIdx.x;
#pragma unroll
    for (int i = 0; i < 16; ++i) {
        int id4 = tid + i * 128;
        int e   = id4 >> 4;            // 0..127
        int j4  = (id4 & 15) << 2;     // 0..60
        int cl  = cbase + j4;
        int h = cl >> 5, f = cl & 31;
        float4 v = *(const float4*)(W + (size_t)h * (Ee * HSs) + e * HSs + f);
        uint4 o;
        o.x = f2tf32(v.x); o.y = f2tf32(v.y); o.z = f2tf32(v.z); o.w = f2tf32(v.w);
        *(uint4*)(Bs + e * GB_STR + j4) = o;
    }
    __syncthreads();

    int w = tid >> 5, lane = tid & 31, grp = lane >> 2, tig = lane & 3;
    int m0 = w * 16;
    float c[8][4];
#pragma unroll
    for (int fn = 0; fn < 8; ++fn)
#pragma unroll
        for (int j = 0; j < 4; ++j) c[fn][j] = 0.f;

    gemm_tile_compute(As, Bs, m0, grp, tig, c);

    float* dst = isV ? g_v : g_k;
#pragma unroll
    for (int fn = 0; fn < 8; ++fn) {
        int cl = cbase + fn * 8 + 2 * tig;
        int h = cl >> 5, f = cl & 31;
        float b0 = bias[h * HSs + f];
        float b1 = bias[h * HSs + f + 1];
        int r = row0 + m0 + grp;
        int bI = r >> 7, cc = r & 127;
        size_t o0 = (((size_t)bI * Hh + h) * Cc + cc) * HSs + f;
        float2 w0 = make_float2(c[fn][0] + b0, c[fn][1] + b1);
        *(float2*)(dst + o0) = w0;
        int r2 = r + 8; bI = r2 >> 7; cc = r2 & 127;
        size_t o1 = (((size_t)bI * Hh + h) * Cc + cc) * HSs + f;
        float2 w1 = make_float2(c[fn][2] + b0, c[fn][3] + b1);
        *(float2*)(dst + o1) = w1;
    }
}

// ---------------- attention: grid (128 bh, 2 qhalf), 256 threads ----------------
// smem: K[128][32] + V[128][32] + S[64][133]
#define ATT_SSTRIDE 133
#define ATT_SMEM (2 * Cc * HSs * 4 + 64 * ATT_SSTRIDE * 4)
__global__ void attn_kernel() {
    extern __shared__ float dsm[];
    float* Kt = dsm;                         // [128][32]
    float* Vt = dsm + Cc * HSs;              // [128][32]
    float* S  = dsm + 2 * Cc * HSs;          // [64][133]
    __shared__ float Sm[4][64];
    __shared__ float Zp[4][64];

    int bh = blockIdx.x;
    int qh = blockIdx.y;
    int b = bh >> 2, h = bh & 3;
    int t = threadIdx.x;          // 0..255
    int qi  = t & 63;
    int c   = qh * 64 + qi;       // global query row
    int qtr = t >> 6;             // 0..3 (key quarter / f quarter)

    const float4* kb4 = (const float4*)(g_k + (size_t)bh * Cc * HSs);
    const float4* vb4 = (const float4*)(g_v + (size_t)bh * Cc * HSs);
#pragma unroll
    for (int i = 0; i < 4; ++i) {
        ((float4*)Kt)[t + i * 256] = kb4[t + i * 256];
        ((float4*)Vt)[t + i * 256] = vb4[t + i * 256];
    }
    __syncthreads();

    float4 kr[8];
    const float4* krow = (const float4*)(Kt + c * HSs);
#pragma unroll
    for (int q = 0; q < 8; ++q) kr[q] = krow[q];

    // scores for keys [qtr*32, qtr*32+32)
    int kb = qtr * 32;
    float mh = -1e30f;
    const float4* K4 = (const float4*)Kt;
#pragma unroll 4
    for (int j = 0; j < 32; ++j) {
        int c2 = kb + j;
        float s0 = 0.f, s1 = 0.f, s2 = 0.f, s3 = 0.f;
#pragma unroll
        for (int q = 0; q < 8; q += 2) {
            float4 a = K4[c2 * 8 + q];
            float4 bq = K4[c2 * 8 + q + 1];
            s0 += kr[q].x * a.x;      s1 += kr[q].y * a.y;
            s2 += kr[q].z * a.z;      s3 += kr[q].w * a.w;
            s0 += kr[q + 1].x * bq.x; s1 += kr[q + 1].y * bq.y;
            s2 += kr[q + 1].z * bq.z; s3 += kr[q + 1].w * bq.w;
        }
        float s = ((s0 + s1) + (s2 + s3)) * SCALE;
        float sv = (c2 <= c) ? s : -INFINITY;
        S[qi * ATT_SSTRIDE + c2] = sv;
        mh = fmaxf(mh, sv);
    }
    Sm[qtr][qi] = mh;
    __syncthreads();
    float m = fmaxf(fmaxf(Sm[0][qi], Sm[1][qi]), fmaxf(Sm[2][qi], Sm[3][qi]));

    float z = 0.f;
#pragma unroll 4
    for (int j = 0; j < 32; ++j) {
        int idx = qi * ATT_SSTRIDE + kb + j;
        float e = __expf(S[idx] - m);
        S[idx] = e;
        z += e;
    }
    Zp[qtr][qi] = z;
    __syncthreads();
    float inv = 1.0f / (Zp[0][qi] + Zp[1][qi] + Zp[2][qi] + Zp[3][qi]);

    // phase 3: O = P @ V for f in [qtr*8, qtr*8+8)
    int fb = qtr * 8;
    float4 a0 = {0,0,0,0}, a1 = {0,0,0,0};
#pragma unroll 4
    for (int c2 = 0; c2 < Cc; ++c2) {
        float p = S[qi * ATT_SSTRIDE + c2];
        float4 v0 = *(const float4*)(Vt + c2 * HSs + fb);
        float4 v1 = *(const float4*)(Vt + c2 * HSs + fb + 4);
        a0.x += p * v0.x; a0.y += p * v0.y; a0.z += p * v0.z; a0.w += p * v0.w;
        a1.x += p * v1.x; a1.y += p * v1.y; a1.z += p * v1.z; a1.w += p * v1.w;
    }
    a0.x *= inv; a0.y *= inv; a0.z *= inv; a0.w *= inv;
    a1.x *= inv; a1.y *= inv; a1.z *= inv; a1.w *= inv;
    float* orow = g_att + ((size_t)(b * Cc + c)) * Ee + h * HSs + fb;
    *(float4*)(orow)     = a0;
    *(float4*)(orow + 4) = a1;
}

// ---------------- output projection + residual via tf32 MMA. grid (2, 64) --------
__global__ __launch_bounds__(128, 3)
void proj_mma_kernel(const float* __restrict__ Wo, const float* __restrict__ bo) {
    extern __shared__ unsigned sm[];
    unsigned* As = sm;
    unsigned* Bs = sm + 64 * GA_STR;

    int row0 = blockIdx.y * 64;
    int n0   = blockIdx.x * 64;

    load_A_tile(As, g_att, row0, Ee, 0);
    load_B_tile(Bs, Wo, Ee, n0, 0);
    __syncthreads();

    int tid = threadIdx.x;
    int w = tid >> 5, lane = tid & 31, grp = lane >> 2, tig = lane & 3;
    int m0 = w * 16;
    float c[8][4];
#pragma unroll
    for (int fn = 0; fn < 8; ++fn)
#pragma unroll
        for (int j = 0; j < 4; ++j) c[fn][j] = 0.f;

    gemm_tile_compute(As, Bs, m0, grp, tig, c);

#pragma unroll
    for (int fn = 0; fn < 8; ++fn) {
        int col = n0 + fn * 8 + 2 * tig;
        float b0 = bo[col], b1 = bo[col + 1];
        int r = row0 + m0 + grp;
        float2* p0 = (float2*)(g_x + (size_t)r * Ee + col);
        float2 x0 = *p0;
        x0.x += c[fn][0] + b0; x0.y += c[fn][1] + b1;
        *p0 = x0;
        float2* p1 = (float2*)(g_x + (size_t)(r + 8) * Ee + col);
        float2 x1 = *p1;
        x1.x += c[fn][2] + b0; x1.y += c[fn][3] + b1;
        *p1 = x1;
    }
}

// ---------------- FFN1 (LN fused): u = relu(LN(x) @ W1 + b1). grid (8, 64) --------
__global__ __launch_bounds__(128, 3)
void ffn1_mma_kernel(const float* __restrict__ W1, const float* __restrict__ b1,
                     const float* __restrict__ ln_g, const float* __restrict__ ln_b) {
    extern __shared__ unsigned sm[];
    unsigned* As = sm;
    unsigned* Bs = sm + 64 * GA_STR;

    int row0 = blockIdx.y * 64;
    int n0   = blockIdx.x * 64;

    load_A_tile_ln(As, g_x, row0, ln_g, ln_b);
    load_B_tile(Bs, W1, FFf, n0, 0);
    __syncthreads();

    int tid = threadIdx.x;
    int w = tid >> 5, lane = tid & 31, grp = lane >> 2, tig = lane & 3;
    int m0 = w * 16;
    float c[8][4];
#pragma unroll
    for (int fn = 0; fn < 8; ++fn)
#pragma unroll
        for (int j = 0; j < 4; ++j) c[fn][j] = 0.f;

    gemm_tile_compute(As, Bs, m0, grp, tig, c);

#pragma unroll
    for (int fn = 0; fn < 8; ++fn) {
        int col = n0 + fn * 8 + 2 * tig;
        float b0 = b1[col], b1v = b1[col + 1];
        int r = row0 + m0 + grp;
        float2 w0 = make_float2(fmaxf(c[fn][0] + b0, 0.f), fmaxf(c[fn][1] + b1v, 0.f));
        *(float2*)(g_u + (size_t)r * FFf + col) = w0;
        float2 w1 = make_float2(fmaxf(c[fn][2] + b0, 0.f), fmaxf(c[fn][3] + b1v, 0.f));
        *(float2*)(g_u + (size_t)(r + 8) * FFf + col) = w1;
    }
}

// ---------------- FFN2 + residual: K=512 in 4 chunks. grid (2, 64) ----------------
__global__ __launch_bounds__(128, 3)
void ffn2_mma_kernel(const float* __restrict__ W2, const float* __restrict__ b2) {
    extern __shared__ unsigned sm[];
    unsigned* As = sm;
    unsigned* Bs = sm + 64 * GA_STR;

    int row0 = blockIdx.y * 64;
    int n0   = blockIdx.x * 64;

    int tid = threadIdx.x;
    int w = tid >> 5, lane = tid & 31, grp = lane >> 2, tig = lane & 3;
    int m0 = w * 16;
    float c[8][4];
#pragma unroll
    for (int fn = 0; fn < 8; ++fn)
#pragma unroll
        for (int j = 0; j < 4; ++j) c[fn][j] = 0.f;

    for (int chunk = 0; chunk < 4; ++chunk) {
        if (chunk) __syncthreads();
        load_A_tile(As, g_u, row0, FFf, chunk * 128);
        load_B_tile(Bs, W2, Ee, n0, chunk * 128);
        __syncthreads();
        gemm_tile_compute(As, Bs, m0, grp, tig, c);
    }

#pragma unroll
    for (int fn = 0; fn < 8; ++fn) {
        int col = n0 + fn * 8 + 2 * tig;
        float b0 = b2[col], b1 = b2[col + 1];
        int r = row0 + m0 + grp;
        float2* p0 = (float2*)(g_x + (size_t)r * Ee + col);
        float2 x0 = *p0;
        x0.x += c[fn][0] + b0; x0.y += c[fn][1] + b1;
        *p0 = x0;
        float2* p1 = (float2*)(g_x + (size_t)(r + 8) * Ee + col);
        float2 x1 = *p1;
        x1.x += c[fn][2] + b0; x1.y += c[fn][3] + b1;
        *p1 = x1;
    }
}

// ---------------- LM head: tf32 mma, BM=256 BN=128 K=128, double-buffered B ------
#define LM_BSTRIDE 136
#define LM_SMEM (2 * 64 * LM_BSTRIDE * 4)   // 69632

#define LM_LOADA(dst, kb) do {                                               \
    dst[0] = A0[(kb) + tig];               dst[1] = A0[8 * Ee + (kb) + tig]; \
    dst[2] = A0[(kb) + 4 + tig];           dst[3] = A0[8 * Ee + (kb) + 4 + tig]; \
    dst[4] = A0[16 * Ee + (kb) + tig];     dst[5] = A0[24 * Ee + (kb) + tig];    \
    dst[6] = A0[16 * Ee + (kb) + 4 + tig]; dst[7] = A0[24 * Ee + (kb) + 4 + tig];\
} while (0)

__global__ __launch_bounds__(512, 1)
void lmhead_kernel(const float* __restrict__ Wf,
                   const float* __restrict__ bf,
                   float* __restrict__ out) {
    extern __shared__ unsigned Bs[];          // [2][64][136]
    int tid  = threadIdx.x;
    int row0 = blockIdx.y * 256;
    int col0 = blockIdx.x * 128;

    // ---- fetch chunk 0 (k rows 0..63), cvt, store ----
    float4 fb4[4];
#pragma unroll
    for (int i = 0; i < 4; ++i) {
        int id4 = tid + i * 512;              // 0..2047
        int k   = id4 >> 5;                   // 0..63
        int c4  = (id4 & 31) << 2;
        int col = col0 + c4;
        float4 bv;
        if (col + 3 < Vv) {
            bv = *(const float4*)(Wf + (size_t)k * Vv + col);
        } else {
            bv.x = (col     < Vv) ? Wf[(size_t)k * Vv + col]     : 0.f;
            bv.y = (col + 1 < Vv) ? Wf[(size_t)k * Vv + col + 1] : 0.f;
            bv.z = (col + 2 < Vv) ? Wf[(size_t)k * Vv + col + 2] : 0.f;
            bv.w = (col + 3 < Vv) ? Wf[(size_t)k * Vv + col + 3] : 0.f;
        }
        fb4[i] = bv;
    }
#pragma unroll
    for (int i = 0; i < 4; ++i) {
        int id4 = tid + i * 512;
        int k   = id4 >> 5;
        int c4  = (id4 & 31) << 2;
        uint4 o;
        o.x = f2tf32(fb4[i].x); o.y = f2tf32(fb4[i].y);
        o.z = f2tf32(fb4[i].z); o.w = f2tf32(fb4[i].w);
        *(uint4*)(&Bs[k * LM_BSTRIDE + c4]) = o;
    }
    __syncthreads();

    // ---- issue LDG for chunk 1 (rows 64..127); hidden under chunk-0 compute ----
#pragma unroll
    for (int i = 0; i < 4; ++i) {
        int id4 = tid + i * 512;
        int k   = (id4 >> 5) + 64;            // 64..127
        int c4  = (id4 & 31) << 2;
        int col = col0 + c4;
        float4 bv;
        if (col + 3 < Vv) {
            bv = *(const float4*)(Wf + (size_t)k * Vv + col);
        } else {
            bv.x = (col     < Vv) ? Wf[(size_t)k * Vv + col]     : 0.f;
            bv.y = (col + 1 < Vv) ? Wf[(size_t)k * Vv + col + 1] : 0.f;
            bv.z = (col + 2 < Vv) ? Wf[(size_t)k * Vv + col + 2] : 0.f;
            bv.w = (col + 3 < Vv) ? Wf[(size_t)k * Vv + col + 3] : 0.f;
        }
        fb4[i] = bv;
    }

    int w    = tid >> 5;
    int lane = tid & 31;
    int grp  = lane >> 2;
    int tig  = lane & 3;
    int n0   = (w & 1) * 64;
    int m0   = (w >> 1) * 32;

    const unsigned* A0 = g_ha + (size_t)(row0 + m0 + grp) * Ee;

    float c[2][8][4];
#pragma unroll
    for (int s = 0; s < 2; ++s)
#pragma unroll
        for (int fn = 0; fn < 8; ++fn)
#pragma unroll
            for (int j = 0; j < 4; ++j) c[s][fn][j] = 0.f;

    unsigned a[8], an[8];
    LM_LOADA(a, 0);

    // ---- chunk 0 compute: k0 = 0..56 ----
#pragma unroll 1
    for (int k0 = 0; k0 < 64; k0 += 8) {
        LM_LOADA(an, k0 + 8);   // k0+8 <= 64 always valid (row0+.. rows, col k<=71<128)
#pragma unroll
        for (int fn = 0; fn < 8; ++fn) {
            unsigned b0 = Bs[(k0 + tig)     * LM_BSTRIDE + n0 + fn * 8 + grp];
            unsigned b1 = Bs[(k0 + 4 + tig) * LM_BSTRIDE + n0 + fn * 8 + grp];
            mma_tf32(c[0][fn], a[0], a[1], a[2], a[3], b0, b1);
            mma_tf32(c[1][fn], a[4], a[5], a[6], a[7], b0, b1);
        }
#pragma unroll
        for (int j = 0; j < 8; ++j) a[j] = an[j];
    }

    // ---- store chunk 1, sync ----
#pragma unroll
    for (int i = 0; i < 4; ++i) {
        int id4 = tid + i * 512;
        int k   = id4 >> 5;
        int c4  = (id4 & 31) << 2;
        uint4 o;
        o.x = f2tf32(fb4[i].x); o.y = f2tf32(fb4[i].y);
        o.z = f2tf32(fb4[i].z); o.w = f2tf32(fb4[i].w);
        *(uint4*)(&Bs[(64 + k) * LM_BSTRIDE + c4]) = o;
    }
    __syncthreads();

    // ---- chunk 1 compute: k0 = 64..120 ----
    const unsigned* B1 = Bs + 64 * LM_BSTRIDE;
#pragma unroll 1
    for (int k0 = 64; k0 < 128; k0 += 8) {
        if (k0 < 120) LM_LOADA(an, k0 + 8);
        int kk = k0 - 64;
#pragma unroll
        for (int fn = 0; fn < 8; ++fn) {
            unsigned b0 = B1[(kk + tig)     * LM_BSTRIDE + n0 + fn * 8 + grp];
            unsigned b1 = B1[(kk + 4 + tig) * LM_BSTRIDE + n0 + fn * 8 + grp];
            mma_tf32(c[0][fn], a[0], a[1], a[2], a[3], b0, b1);
            mma_tf32(c[1][fn], a[4], a[5], a[6], a[7], b0, b1);
        }
#pragma unroll
        for (int j = 0; j < 8; ++j) a[j] = an[j];
    }

    // ---- epilogue ----
#pragma unroll
    for (int s = 0; s < 2; ++s) {
        int ra = row0 + m0 + s * 16 + grp;
#pragma unroll
        for (int fn = 0; fn < 8; ++fn) {
            int colb = col0 + n0 + fn * 8 + 2 * tig;
            if (colb < Vv) {
                float2 bb = *(const float2*)(bf + colb);
                float2 w0, w1;
                w0.x = c[s][fn][0] + bb.x; w0.y = c[s][fn][1] + bb.y;
                w1.x = c[s][fn][2] + bb.x; w1.y = c[s][fn][3] + bb.y;
                *(float2*)(out + (size_t)ra * Vv + colb)       = w0;
                *(float2*)(out + (size_t)(ra + 8) * Vv + colb) = w1;
            }
        }
    }
}

// ---------------- launcher ----------------
extern "C" void kernel_launch(void* const* d_in, const int* in_sizes, int n_in,
                              void* d_out, int out_size) {
    const int*   idx  = (const int*)  d_in[0];
    const float* tok  = (const float*)d_in[1];
    const float* pos  = (const float*)d_in[2];
    const float* Wk   = (const float*)d_in[3];
    const float* bk   = (const float*)d_in[4];
    const float* Wv   = (const float*)d_in[5];
    const float* bv   = (const float*)d_in[6];
    const float* Wo   = (const float*)d_in[7];
    const float* bo   = (const float*)d_in[8];
    const float* W1   = (const float*)d_in[9];
    const float* b1   = (const float*)d_in[10];
    const float* W2   = (const float*)d_in[11];
    const float* b2   = (const float*)d_in[12];
    const float* ln1g = (const float*)d_in[13];
    const float* ln1b = (const float*)d_in[14];
    const float* ln2g = (const float*)d_in[15];
    const float* ln2b = (const float*)d_in[16];
    const float* lnfg = (const float*)d_in[17];
    const float* lnfb = (const float*)d_in[18];
    const float* Wf   = (const float*)d_in[19];
    const float* bf   = (const float*)d_in[20];
    float* out = (float*)d_out;

    static int attr_done = 0;
    if (!attr_done) {
        cudaFuncSetAttribute(attn_kernel,
                             cudaFuncAttributeMaxDynamicSharedMemorySize, ATT_SMEM);
        cudaFuncSetAttribute(lmhead_kernel,
                             cudaFuncAttributeMaxDynamicSharedMemorySize, LM_SMEM);
        cudaFuncSetAttribute(kv_mma_kernel,
                             cudaFuncAttributeMaxDynamicSharedMemorySize, GEMM_SMEM);
        cudaFuncSetAttribute(proj_mma_kernel,
                             cudaFuncAttributeMaxDynamicSharedMemorySize, GEMM_SMEM);
        cudaFuncSetAttribute(ffn1_mma_kernel,
                             cudaFuncAttributeMaxDynamicSharedMemorySize, GEMM_SMEM);
        cudaFuncSetAttribute(ffn2_mma_kernel,
                             cudaFuncAttributeMaxDynamicSharedMemorySize, GEMM_SMEM);
        attr_done = 1;
    }

    embed_kernel<<<Rr, 128>>>(idx, tok, pos);

    for (int l = 0; l < Ll; ++l) {
        kv_mma_kernel<<<dim3(4, 64), 128, GEMM_SMEM>>>(
            Wk + (size_t)l * Hh * Ee * HSs, bk + (size_t)l * Hh * HSs,
            Wv + (size_t)l * Hh * Ee * HSs, bv + (size_t)l * Hh * HSs,
            ln1g + l * Ee, ln1b + l * Ee);
        attn_kernel<<<dim3(Bb * Hh, 2), 256, ATT_SMEM>>>();
        proj_mma_kernel<<<dim3(2, 64), 128, GEMM_SMEM>>>(
            Wo + (size_t)l * Ee * Ee, bo + (size_t)l * Ee);
        ffn1_mma_kernel<<<dim3(8, 64), 128, GEMM_SMEM>>>(
            W1 + (size_t)l * Ee * FFf, b1 + (size_t)l * FFf,
            ln2g + l * Ee, ln2b + l * Ee);
        ffn2_mma_kernel<<<dim3(2, 64), 128, GEMM_SMEM>>>(
            W2 + (size_t)l * FFf * Ee, b2 + (size_t)l * Ee);
    }

    lnf_kernel<<<Rr / 4, 128>>>(lnfg, lnfb);

    dim3 grid((Vv + 127) / 128, Rr / 256);
    lmhead_kernel<<<grid, 512, LM_SMEM>>>(Wf, bf, out);
}

// round 17
// speedup vs baseline: 2.5781x; 1.0353x over previous
#include <cuda_runtime.h>
#include <cuda_bf16.h>
#include <cstddef>

// Problem constants
#define Vv   50000
#define Ee   128
#define Cc   128
#define Hh   4
#define Ll   4
#define HSs  32
#define FFf  512
#define Bb   32
#define Rr   (Bb * Cc)        // 4096 rows
#define SCALE 0.08838834764831845f   // 1/sqrt(128)

// ---------------- scratch (static device globals; no allocation) ----------------
__device__ float g_x[Rr * Ee];         // residual stream
__device__ float g_k[Rr * Ee];         // (B,H,C,HS)
__device__ float g_v[Rr * Ee];         // (B,H,C,HS)
__device__ float g_att[Rr * Ee];       // attention out in (B,C,E)
__device__ float g_u[Rr * FFf];        // FFN intermediate (post-relu)
__device__ unsigned g_ha[Rr * Ee];     // tf32 final-LN activations

// ---------------- tf32 helpers ----------------
__device__ __forceinline__ unsigned f2tf32(float f) {
    unsigned o;
    asm("cvt.rna.tf32.f32 %0, %1;" : "=r"(o) : "f"(f));
    return o;
}

__device__ __forceinline__ void mma_tf32(float c[4],
                                         unsigned a0, unsigned a1, unsigned a2, unsigned a3,
                                         unsigned b0, unsigned b1) {
    asm volatile(
        "mma.sync.aligned.m16n8k8.row.col.f32.tf32.tf32.f32 "
        "{%0,%1,%2,%3}, {%4,%5,%6,%7}, {%8,%9}, {%0,%1,%2,%3};\n"
        : "+f"(c[0]), "+f"(c[1]), "+f"(c[2]), "+f"(c[3])
        : "r"(a0), "r"(a1), "r"(a2), "r"(a3), "r"(b0), "r"(b1));
}

// ---------------- generic tf32 GEMM tile machinery (BM=64, BN=64, Kc=128, 128 thr) ----
#define GA_STR 132
#define GB_STR 72
#define GEMM_SMEM ((64 * GA_STR + 128 * GB_STR) * 4)   // 70656 bytes

__device__ __forceinline__ void load_A_tile(unsigned* As, const float* A,
                                            int row0, int ldA, int koff) {
    int tid = threadIdx.x;
#pragma unroll
    for (int i = 0; i < 16; ++i) {
        int id4 = tid + i * 128;          // 0..2047
        int m   = id4 >> 5;               // 0..63
        int e4  = (id4 & 31) << 2;        // 0..124
        float4 v = *(const float4*)(A + (size_t)(row0 + m) * ldA + koff + e4);
        uint4 o;
        o.x = f2tf32(v.x); o.y = f2tf32(v.y); o.z = f2tf32(v.z); o.w = f2tf32(v.w);
        *(uint4*)(As + m * GA_STR + e4) = o;
    }
}

// LN fused into the A-tile load (unbiased variance, ddof=1).
__device__ __forceinline__ void load_A_tile_ln(unsigned* As, const float* X, int row0,
                                               const float* __restrict__ gg,
                                               const float* __restrict__ bb) {
    int tid  = threadIdx.x;
    int lane = tid & 31;
    float4 G  = ((const float4*)gg)[lane];
    float4 Bc = ((const float4*)bb)[lane];
#pragma unroll
    for (int i = 0; i < 16; ++i) {
        int id4 = tid + i * 128;
        int m   = id4 >> 5;               // warp-uniform row
        int e4  = lane << 2;
        float4 v = *(const float4*)(X + (size_t)(row0 + m) * Ee + e4);
        float s = v.x + v.y + v.z + v.w;
#pragma unroll
        for (int o = 16; o; o >>= 1) s += __shfl_xor_sync(0xffffffffu, s, o);
        float mean = s * (1.0f / Ee);
        float4 d = make_float4(v.x - mean, v.y - mean, v.z - mean, v.w - mean);
        float q = d.x * d.x + d.y * d.y + d.z * d.z + d.w * d.w;
#pragma unroll
        for (int o = 16; o; o >>= 1) q += __shfl_xor_sync(0xffffffffu, q, o);
        float is = rsqrtf(q * (1.0f / (Ee - 1)) + 1e-5f);
        uint4 o4;
        o4.x = f2tf32(d.x * is * G.x + Bc.x);
        o4.y = f2tf32(d.y * is * G.y + Bc.y);
        o4.z = f2tf32(d.z * is * G.z + Bc.z);
        o4.w = f2tf32(d.w * is * G.w + Bc.w);
        *(uint4*)(As + m * GA_STR + e4) = o4;
    }
}

__device__ __forceinline__ void load_B_tile(unsigned* Bs, const float* B,
                                            int ldB, int n0, int krow0) {
    int tid = threadIdx.x;
#pragma unroll
    for (int i = 0; i < 16; ++i) {
        int id4 = tid + i * 128;          // 0..2047
        int k   = id4 >> 4;               // 0..127
        int n4  = (id4 & 15) << 2;        // 0..60
        float4 v = *(const float4*)(B + (size_t)(krow0 + k) * ldB + n0 + n4);
        uint4 o;
        o.x = f2tf32(v.x); o.y = f2tf32(v.y); o.z = f2tf32(v.z); o.w = f2tf32(v.w);
        *(uint4*)(Bs + k * GB_STR + n4) = o;
    }
}

__device__ __forceinline__ void gemm_tile_compute(const unsigned* As, const unsigned* Bs,
                                                  int m0, int grp, int tig,
                                                  float c[8][4]) {
#pragma unroll 4
    for (int k0 = 0; k0 < 128; k0 += 8) {
        unsigned a0 = As[(m0 + grp)     * GA_STR + k0 + tig];
        unsigned a1 = As[(m0 + grp + 8) * GA_STR + k0 + tig];
        unsigned a2 = As[(m0 + grp)     * GA_STR + k0 + 4 + tig];
        unsigned a3 = As[(m0 + grp + 8) * GA_STR + k0 + 4 + tig];
#pragma unroll
        for (int fn = 0; fn < 8; ++fn) {
            unsigned b0 = Bs[(k0 + tig)     * GB_STR + fn * 8 + grp];
            unsigned b1 = Bs[(k0 + 4 + tig) * GB_STR + fn * 8 + grp];
            mma_tf32(c[fn], a0, a1, a2, a3, b0, b1);
        }
    }
}

// ---------------- embedding gather ----------------
__global__ void embed_kernel(const int* __restrict__ idx,
                             const float* __restrict__ te,
                             const float* __restrict__ pe) {
    int r = blockIdx.x;
    int t = threadIdx.x;
    int tok = idx[r];
    size_t off = (size_t)tok * Ee + t;
    g_x[r * Ee + t] = te[off] + pe[off];
}

// ---------------- final LayerNorm (biased) -> tf32 activations ----------------
__global__ void lnf_kernel(const float* __restrict__ gg,
                           const float* __restrict__ bb) {
    int r = blockIdx.x * 4 + (threadIdx.x >> 5);
    int lane = threadIdx.x & 31;
    float4 v = ((const float4*)(g_x + (size_t)r * Ee))[lane];
    float s = v.x + v.y + v.z + v.w;
#pragma unroll
    for (int o = 16; o; o >>= 1) s += __shfl_xor_sync(0xffffffffu, s, o);
    float mean = s * (1.0f / Ee);
    float4 d = make_float4(v.x - mean, v.y - mean, v.z - mean, v.w - mean);
    float q = d.x * d.x + d.y * d.y + d.z * d.z + d.w * d.w;
#pragma unroll
    for (int o = 16; o; o >>= 1) q += __shfl_xor_sync(0xffffffffu, q, o);
    float var = q * (1.0f / Ee);
    float is = rsqrtf(var + 1e-5f);
    float4 G = ((const float4*)gg)[lane];
    float4 Bc = ((const float4*)bb)[lane];
    uint4 o4;
    o4.x = f2tf32(d.x * is * G.x + Bc.x);
    o4.y = f2tf32(d.y * is * G.y + Bc.y);
    o4.z = f2tf32(d.z * is * G.z + Bc.z);
    o4.w = f2tf32(d.w * is * G.w + Bc.w);
    ((uint4*)(g_ha + (size_t)r * Ee))[lane] = o4;
}

// ---------------- K/V projection via tf32 MMA (LN fused in A-load) ----------------
// grid (4, 64): x-blocks over 256 output cols [k:128 | v:128], y over rows.
__global__ __launch_bounds__(128, 3)
void kv_mma_kernel(const float* __restrict__ Wk, const float* __restrict__ bk,
                   const float* __restrict__ Wv, const float* __restrict__ bv,
                   const float* __restrict__ ln_g, const float* __restrict__ ln_b) {
    extern __shared__ unsigned sm[];
    unsigned* As = sm;
    unsigned* Bs = sm + 64 * GA_STR;

    int row0  = blockIdx.y * 64;
    int n0g   = blockIdx.x * 64;       // 0,64,128,192
    int isV   = n0g >= 128;
    const float* W    = isV ? Wv : Wk;
    const float* bias = isV ? bv : bk;
    int cbase = n0g & 127;             // 0 or 64

    load_A_tile_ln(As, g_x, row0, ln_g, ln_b);

    int tid = threadIdx.x;
#pragma unroll
    for (int i = 0; i < 16; ++i) {
        int id4 = tid + i * 128;
        int e   = id4 >> 4;            // 0..127
        int j4  = (id4 & 15) << 2;     // 0..60
        int cl  = cbase + j4;
        int h = cl >> 5, f = cl & 31;
        float4 v = *(const float4*)(W + (size_t)h * (Ee * HSs) + e * HSs + f);
        uint4 o;
        o.x = f2tf32(v.x); o.y = f2tf32(v.y); o.z = f2tf32(v.z); o.w = f2tf32(v.w);
        *(uint4*)(Bs + e * GB_STR + j4) = o;
    }
    __syncthreads();

    int w = tid >> 5, lane = tid & 31, grp = lane >> 2, tig = lane & 3;
    int m0 = w * 16;
    float c[8][4];
#pragma unroll
    for (int fn = 0; fn < 8; ++fn)
#pragma unroll
        for (int j = 0; j < 4; ++j) c[fn][j] = 0.f;

    gemm_tile_compute(As, Bs, m0, grp, tig, c);

    float* dst = isV ? g_v : g_k;
#pragma unroll
    for (int fn = 0; fn < 8; ++fn) {
        int cl = cbase + fn * 8 + 2 * tig;
        int h = cl >> 5, f = cl & 31;
        float b0 = bias[h * HSs + f];
        float b1 = bias[h * HSs + f + 1];
        int r = row0 + m0 + grp;
        int bI = r >> 7, cc = r & 127;
        size_t o0 = (((size_t)bI * Hh + h) * Cc + cc) * HSs + f;
        float2 w0 = make_float2(c[fn][0] + b0, c[fn][1] + b1);
        *(float2*)(dst + o0) = w0;
        int r2 = r + 8; bI = r2 >> 7; cc = r2 & 127;
        size_t o1 = (((size_t)bI * Hh + h) * Cc + cc) * HSs + f;
        float2 w1 = make_float2(c[fn][2] + b0, c[fn][3] + b1);
        *(float2*)(dst + o1) = w1;
    }
}

// ---------------- attention: grid (128 bh, 2 qhalf), 256 threads ----------------
#define ATT_SSTRIDE 133
#define ATT_SMEM (2 * Cc * HSs * 4 + 64 * ATT_SSTRIDE * 4)
__global__ void attn_kernel() {
    extern __shared__ float dsm[];
    float* Kt = dsm;                         // [128][32]
    float* Vt = dsm + Cc * HSs;              // [128][32]
    float* S  = dsm + 2 * Cc * HSs;          // [64][133]
    __shared__ float Sm[4][64];
    __shared__ float Zp[4][64];

    int bh = blockIdx.x;
    int qh = blockIdx.y;
    int b = bh >> 2, h = bh & 3;
    int t = threadIdx.x;          // 0..255
    int qi  = t & 63;
    int c   = qh * 64 + qi;       // global query row
    int qtr = t >> 6;             // 0..3

    const float4* kb4 = (const float4*)(g_k + (size_t)bh * Cc * HSs);
    const float4* vb4 = (const float4*)(g_v + (size_t)bh * Cc * HSs);
#pragma unroll
    for (int i = 0; i < 4; ++i) {
        ((float4*)Kt)[t + i * 256] = kb4[t + i * 256];
        ((float4*)Vt)[t + i * 256] = vb4[t + i * 256];
    }
    __syncthreads();

    float4 kr[8];
    const float4* krow = (const float4*)(Kt + c * HSs);
#pragma unroll
    for (int q = 0; q < 8; ++q) kr[q] = krow[q];

    int kb = qtr * 32;
    float mh = -1e30f;
    const float4* K4 = (const float4*)Kt;
#pragma unroll 4
    for (int j = 0; j < 32; ++j) {
        int c2 = kb + j;
        float s0 = 0.f, s1 = 0.f, s2 = 0.f, s3 = 0.f;
#pragma unroll
        for (int q = 0; q < 8; q += 2) {
            float4 a = K4[c2 * 8 + q];
            float4 bq = K4[c2 * 8 + q + 1];
            s0 += kr[q].x * a.x;      s1 += kr[q].y * a.y;
            s2 += kr[q].z * a.z;      s3 += kr[q].w * a.w;
            s0 += kr[q + 1].x * bq.x; s1 += kr[q + 1].y * bq.y;
            s2 += kr[q + 1].z * bq.z; s3 += kr[q + 1].w * bq.w;
        }
        float s = ((s0 + s1) + (s2 + s3)) * SCALE;
        float sv = (c2 <= c) ? s : -INFINITY;
        S[qi * ATT_SSTRIDE + c2] = sv;
        mh = fmaxf(mh, sv);
    }
    Sm[qtr][qi] = mh;
    __syncthreads();
    float m = fmaxf(fmaxf(Sm[0][qi], Sm[1][qi]), fmaxf(Sm[2][qi], Sm[3][qi]));

    float z = 0.f;
#pragma unroll 4
    for (int j = 0; j < 32; ++j) {
        int idx = qi * ATT_SSTRIDE + kb + j;
        float e = __expf(S[idx] - m);
        S[idx] = e;
        z += e;
    }
    Zp[qtr][qi] = z;
    __syncthreads();
    float inv = 1.0f / (Zp[0][qi] + Zp[1][qi] + Zp[2][qi] + Zp[3][qi]);

    int fb = qtr * 8;
    float4 a0 = {0,0,0,0}, a1 = {0,0,0,0};
#pragma unroll 4
    for (int c2 = 0; c2 < Cc; ++c2) {
        float p = S[qi * ATT_SSTRIDE + c2];
        float4 v0 = *(const float4*)(Vt + c2 * HSs + fb);
        float4 v1 = *(const float4*)(Vt + c2 * HSs + fb + 4);
        a0.x += p * v0.x; a0.y += p * v0.y; a0.z += p * v0.z; a0.w += p * v0.w;
        a1.x += p * v1.x; a1.y += p * v1.y; a1.z += p * v1.z; a1.w += p * v1.w;
    }
    a0.x *= inv; a0.y *= inv; a0.z *= inv; a0.w *= inv;
    a1.x *= inv; a1.y *= inv; a1.z *= inv; a1.w *= inv;
    float* orow = g_att + ((size_t)(b * Cc + c)) * Ee + h * HSs + fb;
    *(float4*)(orow)     = a0;
    *(float4*)(orow + 4) = a1;
}

// ---------------- output projection + residual via tf32 MMA. grid (2, 64) --------
__global__ __launch_bounds__(128, 3)
void proj_mma_kernel(const float* __restrict__ Wo, const float* __restrict__ bo) {
    extern __shared__ unsigned sm[];
    unsigned* As = sm;
    unsigned* Bs = sm + 64 * GA_STR;

    int row0 = blockIdx.y * 64;
    int n0   = blockIdx.x * 64;

    load_A_tile(As, g_att, row0, Ee, 0);
    load_B_tile(Bs, Wo, Ee, n0, 0);
    __syncthreads();

    int tid = threadIdx.x;
    int w = tid >> 5, lane = tid & 31, grp = lane >> 2, tig = lane & 3;
    int m0 = w * 16;
    float c[8][4];
#pragma unroll
    for (int fn = 0; fn < 8; ++fn)
#pragma unroll
        for (int j = 0; j < 4; ++j) c[fn][j] = 0.f;

    gemm_tile_compute(As, Bs, m0, grp, tig, c);

#pragma unroll
    for (int fn = 0; fn < 8; ++fn) {
        int col = n0 + fn * 8 + 2 * tig;
        float b0 = bo[col], b1 = bo[col + 1];
        int r = row0 + m0 + grp;
        float2* p0 = (float2*)(g_x + (size_t)r * Ee + col);
        float2 x0 = *p0;
        x0.x += c[fn][0] + b0; x0.y += c[fn][1] + b1;
        *p0 = x0;
        float2* p1 = (float2*)(g_x + (size_t)(r + 8) * Ee + col);
        float2 x1 = *p1;
        x1.x += c[fn][2] + b0; x1.y += c[fn][3] + b1;
        *p1 = x1;
    }
}

// ---------------- FFN1 (LN fused): u = relu(LN(x) @ W1 + b1). grid (8, 64) --------
__global__ __launch_bounds__(128, 3)
void ffn1_mma_kernel(const float* __restrict__ W1, const float* __restrict__ b1,
                     const float* __restrict__ ln_g, const float* __restrict__ ln_b) {
    extern __shared__ unsigned sm[];
    unsigned* As = sm;
    unsigned* Bs = sm + 64 * GA_STR;

    int row0 = blockIdx.y * 64;
    int n0   = blockIdx.x * 64;

    load_A_tile_ln(As, g_x, row0, ln_g, ln_b);
    load_B_tile(Bs, W1, FFf, n0, 0);
    __syncthreads();

    int tid = threadIdx.x;
    int w = tid >> 5, lane = tid & 31, grp = lane >> 2, tig = lane & 3;
    int m0 = w * 16;
    float c[8][4];
#pragma unroll
    for (int fn = 0; fn < 8; ++fn)
#pragma unroll
        for (int j = 0; j < 4; ++j) c[fn][j] = 0.f;

    gemm_tile_compute(As, Bs, m0, grp, tig, c);

#pragma unroll
    for (int fn = 0; fn < 8; ++fn) {
        int col = n0 + fn * 8 + 2 * tig;
        float b0 = b1[col], b1v = b1[col + 1];
        int r = row0 + m0 + grp;
        float2 w0 = make_float2(fmaxf(c[fn][0] + b0, 0.f), fmaxf(c[fn][1] + b1v, 0.f));
        *(float2*)(g_u + (size_t)r * FFf + col) = w0;
        float2 w1 = make_float2(fmaxf(c[fn][2] + b0, 0.f), fmaxf(c[fn][3] + b1v, 0.f));
        *(float2*)(g_u + (size_t)(r + 8) * FFf + col) = w1;
    }
}

// ---------------- FFN2 + residual: K=512 in 4 chunks. grid (2, 64) ----------------
__global__ __launch_bounds__(128, 3)
void ffn2_mma_kernel(const float* __restrict__ W2, const float* __restrict__ b2) {
    extern __shared__ unsigned sm[];
    unsigned* As = sm;
    unsigned* Bs = sm + 64 * GA_STR;

    int row0 = blockIdx.y * 64;
    int n0   = blockIdx.x * 64;

    int tid = threadIdx.x;
    int w = tid >> 5, lane = tid & 31, grp = lane >> 2, tig = lane & 3;
    int m0 = w * 16;
    float c[8][4];
#pragma unroll
    for (int fn = 0; fn < 8; ++fn)
#pragma unroll
        for (int j = 0; j < 4; ++j) c[fn][j] = 0.f;

    for (int chunk = 0; chunk < 4; ++chunk) {
        if (chunk) __syncthreads();
        load_A_tile(As, g_u, row0, FFf, chunk * 128);
        load_B_tile(Bs, W2, Ee, n0, chunk * 128);
        __syncthreads();
        gemm_tile_compute(As, Bs, m0, grp, tig, c);
    }

#pragma unroll
    for (int fn = 0; fn < 8; ++fn) {
        int col = n0 + fn * 8 + 2 * tig;
        float b0 = b2[col], b1 = b2[col + 1];
        int r = row0 + m0 + grp;
        float2* p0 = (float2*)(g_x + (size_t)r * Ee + col);
        float2 x0 = *p0;
        x0.x += c[fn][0] + b0; x0.y += c[fn][1] + b1;
        *p0 = x0;
        float2* p1 = (float2*)(g_x + (size_t)(r + 8) * Ee + col);
        float2 x1 = *p1;
        x1.x += c[fn][2] + b0; x1.y += c[fn][3] + b1;
        *p1 = x1;
    }
}

// ---------------- LM head: tf32 mma, BM=128 BN=128 K=128, 256 thr, 2 CTAs/SM -----
// smem: one 64-k-row B buffer [64][136] u32 = 34816 bytes; K processed in 2 chunks.
// Cross-CTA overlap (2 CTAs/SM) hides the load+cvt phase under the peer's MMAs.
#define LM_BSTRIDE 136
#define LM_SMEM (64 * LM_BSTRIDE * 4)   // 34816

#define LM_LOADA(dst, kb) do {                                               \
    dst[0] = A0[(kb) + tig];               dst[1] = A0[8 * Ee + (kb) + tig]; \
    dst[2] = A0[(kb) + 4 + tig];           dst[3] = A0[8 * Ee + (kb) + 4 + tig]; \
    dst[4] = A0[16 * Ee + (kb) + tig];     dst[5] = A0[24 * Ee + (kb) + tig];    \
    dst[6] = A0[16 * Ee + (kb) + 4 + tig]; dst[7] = A0[24 * Ee + (kb) + 4 + tig];\
} while (0)

__global__ __launch_bounds__(256, 2)
void lmhead_kernel(const float* __restrict__ Wf,
                   const float* __restrict__ bf,
                   float* __restrict__ out) {
    extern __shared__ unsigned Bs[];          // [64][136]
    int tid  = threadIdx.x;
    int row0 = blockIdx.y * 128;
    int col0 = blockIdx.x * 128;

    int w    = tid >> 5;                      // 0..7
    int lane = tid & 31;
    int grp  = lane >> 2;
    int tig  = lane & 3;
    int n0   = (w & 1) * 64;
    int m0   = (w >> 1) * 32;                 // 0,32,64,96

    const unsigned* A0 = g_ha + (size_t)(row0 + m0 + grp) * Ee;

    float c[2][8][4];
#pragma unroll
    for (int s = 0; s < 2; ++s)
#pragma unroll
        for (int fn = 0; fn < 8; ++fn)
#pragma unroll
            for (int j = 0; j < 4; ++j) c[s][fn][j] = 0.f;

    unsigned a[8], an[8];
    LM_LOADA(a, 0);

#pragma unroll 1
    for (int ch = 0; ch < 2; ++ch) {
        // load + convert 64 k-rows x 128 cols of Wf into Bs
#pragma unroll
        for (int i = 0; i < 8; ++i) {
            int id4 = tid + i * 256;          // 0..2047
            int k   = id4 >> 5;               // 0..63
            int c4  = (id4 & 31) << 2;
            int col = col0 + c4;
            float4 bv;
            if (col + 3 < Vv) {
                bv = *(const float4*)(Wf + (size_t)(ch * 64 + k) * Vv + col);
            } else {
                bv.x = (col     < Vv) ? Wf[(size_t)(ch * 64 + k) * Vv + col]     : 0.f;
                bv.y = (col + 1 < Vv) ? Wf[(size_t)(ch * 64 + k) * Vv + col + 1] : 0.f;
                bv.z = (col + 2 < Vv) ? Wf[(size_t)(ch * 64 + k) * Vv + col + 2] : 0.f;
                bv.w = (col + 3 < Vv) ? Wf[(size_t)(ch * 64 + k) * Vv + col + 3] : 0.f;
            }
            uint4 o;
            o.x = f2tf32(bv.x); o.y = f2tf32(bv.y);
            o.z = f2tf32(bv.z); o.w = f2tf32(bv.w);
            *(uint4*)(&Bs[k * LM_BSTRIDE + c4]) = o;
        }
        __syncthreads();

        int kbase = ch * 64;
#pragma unroll 1
        for (int k0 = 0; k0 < 64; k0 += 8) {
            int kg = kbase + k0;
            if (kg < 120) LM_LOADA(an, kg + 8);
#pragma unroll
            for (int fn = 0; fn < 8; ++fn) {
                unsigned b0 = Bs[(k0 + tig)     * LM_BSTRIDE + n0 + fn * 8 + grp];
                unsigned b1 = Bs[(k0 + 4 + tig) * LM_BSTRIDE + n0 + fn * 8 + grp];
                mma_tf32(c[0][fn], a[0], a[1], a[2], a[3], b0, b1);
                mma_tf32(c[1][fn], a[4], a[5], a[6], a[7], b0, b1);
            }
#pragma unroll
            for (int j = 0; j < 8; ++j) a[j] = an[j];
        }
        __syncthreads();
    }

    // epilogue
#pragma unroll
    for (int s = 0; s < 2; ++s) {
        int ra = row0 + m0 + s * 16 + grp;
#pragma unroll
        for (int fn = 0; fn < 8; ++fn) {
            int colb = col0 + n0 + fn * 8 + 2 * tig;
            if (colb < Vv) {
                float2 bb = *(const float2*)(bf + colb);
                float2 w0, w1;
                w0.x = c[s][fn][0] + bb.x; w0.y = c[s][fn][1] + bb.y;
                w1.x = c[s][fn][2] + bb.x; w1.y = c[s][fn][3] + bb.y;
                *(float2*)(out + (size_t)ra * Vv + colb)       = w0;
                *(float2*)(out + (size_t)(ra + 8) * Vv + colb) = w1;
            }
        }
    }
}

// ---------------- launcher ----------------
extern "C" void kernel_launch(void* const* d_in, const int* in_sizes, int n_in,
                              void* d_out, int out_size) {
    const int*   idx  = (const int*)  d_in[0];
    const float* tok  = (const float*)d_in[1];
    const float* pos  = (const float*)d_in[2];
    const float* Wk   = (const float*)d_in[3];
    const float* bk   = (const float*)d_in[4];
    const float* Wv   = (const float*)d_in[5];
    const float* bv   = (const float*)d_in[6];
    const float* Wo   = (const float*)d_in[7];
    const float* bo   = (const float*)d_in[8];
    const float* W1   = (const float*)d_in[9];
    const float* b1   = (const float*)d_in[10];
    const float* W2   = (const float*)d_in[11];
    const float* b2   = (const float*)d_in[12];
    const float* ln1g = (const float*)d_in[13];
    const float* ln1b = (const float*)d_in[14];
    const float* ln2g = (const float*)d_in[15];
    const float* ln2b = (const float*)d_in[16];
    const float* lnfg = (const float*)d_in[17];
    const float* lnfb = (const float*)d_in[18];
    const float* Wf   = (const float*)d_in[19];
    const float* bf   = (const float*)d_in[20];
    float* out = (float*)d_out;

    static int attr_done = 0;
    if (!attr_done) {
        cudaFuncSetAttribute(attn_kernel,
                             cudaFuncAttributeMaxDynamicSharedMemorySize, ATT_SMEM);
        cudaFuncSetAttribute(lmhead_kernel,
                             cudaFuncAttributeMaxDynamicSharedMemorySize, LM_SMEM);
        cudaFuncSetAttribute(kv_mma_kernel,
                             cudaFuncAttributeMaxDynamicSharedMemorySize, GEMM_SMEM);
        cudaFuncSetAttribute(proj_mma_kernel,
                             cudaFuncAttributeMaxDynamicSharedMemorySize, GEMM_SMEM);
        cudaFuncSetAttribute(ffn1_mma_kernel,
                             cudaFuncAttributeMaxDynamicSharedMemorySize, GEMM_SMEM);
        cudaFuncSetAttribute(ffn2_mma_kernel,
                             cudaFuncAttributeMaxDynamicSharedMemorySize, GEMM_SMEM);
        attr_done = 1;
    }

    embed_kernel<<<Rr, 128>>>(idx, tok, pos);

    for (int l = 0; l < Ll; ++l) {
        kv_mma_kernel<<<dim3(4, 64), 128, GEMM_SMEM>>>(
            Wk + (size_t)l * Hh * Ee * HSs, bk + (size_t)l * Hh * HSs,
            Wv + (size_t)l * Hh * Ee * HSs, bv + (size_t)l * Hh * HSs,
            ln1g + l * Ee, ln1b + l * Ee);
        attn_kernel<<<dim3(Bb * Hh, 2), 256, ATT_SMEM>>>();
        proj_mma_kernel<<<dim3(2, 64), 128, GEMM_SMEM>>>(
            Wo + (size_t)l * Ee * Ee, bo + (size_t)l * Ee);
        ffn1_mma_kernel<<<dim3(8, 64), 128, GEMM_SMEM>>>(
            W1 + (size_t)l * Ee * FFf, b1 + (size_t)l * FFf,
            ln2g + l * Ee, ln2b + l * Ee);
        ffn2_mma_kernel<<<dim3(2, 64), 128, GEMM_SMEM>>>(
            W2 + (size_t)l * FFf * Ee, b2 + (size_t)l * Ee);
    }

    lnf_kernel<<<Rr / 4, 128>>>(lnfg, lnfb);

    dim3 grid((Vv + 127) / 128, Rr / 128);
    lmhead_kernel<<<grid, 256, LM_SMEM>>>(Wf, bf, out);
}